// round 10
// baseline (speedup 1.0000x reference)
#include <cuda_runtime.h>
#include <cuda_fp16.h>
#include <cstdint>
#include <math.h>

// ===========================================================================
// VisionAttention (sm_103): fp16 2-product HMMA GEMMs (BM templated; out-proj
// BM=64 @ 3 CTA/SM single-wave) + persistent-segment HMMA attention with
// fused rope/splits. 4 launches.
// ===========================================================================

#define S_LEN 2048
#define HID   1280
#define NHEAD 16
#define HDIM  80
#define QKV_N (3 * HID)   // 3840
#define SEG   256
#define NSEG  8

// ---------------- device scratch ----------------
__device__ __align__(256) float g_qkv[S_LEN * QKV_N];
__device__ __align__(256) __half g_xh[S_LEN * HID];
__device__ __align__(256) __half g_xl[S_LEN * HID];
__device__ __align__(256) __half g_ah[S_LEN * HID];
__device__ __align__(256) __half g_al[S_LEN * HID];
__device__ __align__(256) __half g_wq[QKV_N * HID];   // [N][K] fp16
__device__ __align__(256) __half g_wo[HID * HID];

__device__ __forceinline__ uint32_t smem_to_u32(const void* p) {
    uint32_t a;
    asm("{ .reg .u64 t; cvta.to.shared.u64 t, %1; cvt.u32.u64 %0, t; }"
        : "=r"(a) : "l"(p));
    return a;
}

#define CP_ASYNC16(sa, gp) \
    asm volatile("cp.async.cg.shared.global [%0], [%1], 16;" \
        :: "r"(sa), "l"(gp) : "memory")
#define CP_COMMIT() asm volatile("cp.async.commit_group;" ::: "memory")

#define MMA_F16(ac, a, b) \
    asm volatile("mma.sync.aligned.m16n8k16.row.col.f32.f16.f16.f32 " \
        "{%0,%1,%2,%3},{%4,%5,%6,%7},{%8,%9},{%0,%1,%2,%3};" \
        : "+f"((ac)[0]), "+f"((ac)[1]), "+f"((ac)[2]), "+f"((ac)[3]) \
        : "r"((a)[0]), "r"((a)[1]), "r"((a)[2]), "r"((a)[3]), \
          "r"((b)[0]), "r"((b)[1]))

#define LDSM_X4(r0, r1, r2, r3, addr) \
    asm volatile("ldmatrix.sync.aligned.m8n8.x4.shared.b16 {%0,%1,%2,%3}, [%4];" \
        : "=r"(r0), "=r"(r1), "=r"(r2), "=r"(r3) : "r"(addr))
#define LDSM_X4T(r0, r1, r2, r3, addr) \
    asm volatile("ldmatrix.sync.aligned.m8n8.x4.trans.shared.b16 {%0,%1,%2,%3}, [%4];" \
        : "=r"(r0), "=r"(r1), "=r"(r2), "=r"(r3) : "r"(addr))
#define LDSM_X2T(r0, r1, addr) \
    asm volatile("ldmatrix.sync.aligned.m8n8.x2.trans.shared.b16 {%0,%1}, [%2];" \
        : "=r"(r0), "=r"(r1) : "r"(addr))

__device__ __forceinline__ void split2h(float2 p, uint32_t& hi, uint32_t& lo) {
    __half hx = __float2half_rn(p.x);
    __half hy = __float2half_rn(p.y);
    __half lx = __float2half_rn(p.x - __half2float(hx));
    __half ly = __float2half_rn(p.y - __half2float(hy));
    hi = (uint32_t)__half_as_ushort(hx) | ((uint32_t)__half_as_ushort(hy) << 16);
    lo = (uint32_t)__half_as_ushort(lx) | ((uint32_t)__half_as_ushort(ly) << 16);
}

// ---------------------------------------------------------------------------
// Merged prep: 1 launch.
// ---------------------------------------------------------------------------
__device__ __forceinline__ void transpose_tile(const float* __restrict__ W,
                                               __half* __restrict__ Wt,
                                               int K, int N, int bn, int bk,
                                               int tx, int ty, float* t) {
#pragma unroll
    for (int i = 0; i < 4; i++)
        t[(ty + i * 8) * 33 + tx] = W[(size_t)(bk * 32 + ty + i * 8) * N + bn * 32 + tx];
    __syncthreads();
#pragma unroll
    for (int i = 0; i < 4; i++)
        Wt[(size_t)(bn * 32 + ty + i * 8) * K + bk * 32 + tx] =
            __float2half_rn(t[tx * 33 + ty + i * 8]);
}

__global__ void prep_kernel(const float* __restrict__ x,
                            const float* __restrict__ Wq,
                            const float* __restrict__ Wo,
                            __half* __restrict__ xh, __half* __restrict__ xl,
                            __half* __restrict__ wq, __half* __restrict__ wo) {
    __shared__ float t[32 * 33];
    const int b = blockIdx.x;
    const int tid = threadIdx.x;
    if (b < 2560) {
        int i = (b * 256 + tid) * 4;
        float4 a = *(const float4*)&x[i];
        uint32_t h0, l0, h1, l1;
        split2h(make_float2(a.x, a.y), h0, l0);
        split2h(make_float2(a.z, a.w), h1, l1);
        ((uint32_t*)xh)[i >> 1]       = h0;
        ((uint32_t*)xh)[(i >> 1) + 1] = h1;
        ((uint32_t*)xl)[i >> 1]       = l0;
        ((uint32_t*)xl)[(i >> 1) + 1] = l1;
    } else if (b < 7360) {
        int j = b - 2560;
        transpose_tile(Wq, wq, HID, QKV_N, j % 120, j / 120, tid & 31, tid >> 5, t);
    } else {
        int j = b - 7360;
        transpose_tile(Wo, wo, HID, HID, j % 40, j / 40, tid & 31, tid >> 5, t);
    }
}

// ---------------------------------------------------------------------------
// fp16 2-product GEMM, BM + minBlocks templated. BN=128, BK=32, 2-stage.
// ---------------------------------------------------------------------------
template <int BM, int MINB>
__global__ __launch_bounds__(256, MINB)
void gemm_f16x2_kernel(int M, int N, int K,
                       const __half* __restrict__ Ah,
                       const __half* __restrict__ Al,
                       const __half* __restrict__ B,
                       const float* __restrict__ bias,
                       float* __restrict__ C) {
    constexpr int MT      = BM / 32;
    constexpr int A_TILE  = BM * 80;
    constexpr int B_TILE  = 128 * 80;
    constexpr int STAGE   = 2 * A_TILE + B_TILE;
    constexpr int A_CHUNK = BM * 8;
    constexpr int CP_IT   = (A_CHUNK + 512) / 256;

    extern __shared__ __align__(16) char smem[];
    const uint32_t sbase = smem_to_u32(smem);

    const int tid  = threadIdx.x;
    const int wid  = tid >> 5;
    const int lane = tid & 31;
    const int g    = lane >> 2;
    const int tig  = lane & 3;
    const int wm   = wid & 1;
    const int wn   = wid >> 1;
    const int n0   = blockIdx.x * 128;
    const int m0   = blockIdx.y * BM;

    const __half* srcs[3] = {
        Ah + (size_t)m0 * K, Al + (size_t)m0 * K, B + (size_t)n0 * K };

    float acc[MT][4][4];
#pragma unroll
    for (int i = 0; i < MT; i++)
#pragma unroll
        for (int j = 0; j < 4; j++)
#pragma unroll
            for (int r = 0; r < 4; r++) acc[i][j][r] = 0.f;

    const int KT = K / 32;

    auto issue_stage = [&](int buf, int kt) {
#pragma unroll
        for (int i = 0; i < CP_IT; i++) {
            int c = tid + i * 256;
            uint32_t sa;
            const __half* gp;
            if (c < A_CHUNK) {
                int tile = c / (BM * 4);
                int rem  = c % (BM * 4);
                int row  = rem >> 2, c16 = rem & 3;
                gp = srcs[tile] + (size_t)row * K + kt * 32 + c16 * 8;
                sa = sbase + buf * STAGE + tile * A_TILE + row * 80 + c16 * 16;
            } else {
                int cc  = c - A_CHUNK;
                int row = cc >> 2, c16 = cc & 3;
                gp = srcs[2] + (size_t)row * K + kt * 32 + c16 * 8;
                sa = sbase + buf * STAGE + 2 * A_TILE + row * 80 + c16 * 16;
            }
            CP_ASYNC16(sa, gp);
        }
        CP_COMMIT();
    };

    const uint32_t aOff = (uint32_t)(wm * (BM / 2) + (lane & 15)) * 80 + ((lane >> 4) & 1) * 16;
    const uint32_t bOff = (uint32_t)(wn * 32 + (lane & 15)) * 80 + ((lane >> 4) & 1) * 16;

    issue_stage(0, 0);

    for (int kt = 0; kt < KT; kt++) {
        const int buf = kt & 1;
        if (kt + 1 < KT) {
            issue_stage(buf ^ 1, kt + 1);
            asm volatile("cp.async.wait_group 1;" ::: "memory");
        } else {
            asm volatile("cp.async.wait_group 0;" ::: "memory");
        }
        __syncthreads();

        const uint32_t stage = sbase + buf * STAGE;
        const uint32_t aAh = stage + aOff;
        const uint32_t aAl = aAh + A_TILE;
        const uint32_t aB  = stage + 2 * A_TILE + bOff;

#pragma unroll
        for (int ks = 0; ks < 2; ks++) {
            const uint32_t ko = ks * 32;
            uint32_t bq[4][2];
#pragma unroll
            for (int np = 0; np < 2; np++)
                LDSM_X4(bq[np*2][0], bq[np*2+1][0], bq[np*2][1], bq[np*2+1][1],
                        aB + np * (16 * 80) + ko);
            uint32_t ah[MT][4], al[MT][4];
#pragma unroll
            for (int mt = 0; mt < MT; mt++) {
                LDSM_X4(ah[mt][0], ah[mt][1], ah[mt][2], ah[mt][3],
                        aAh + mt * (16 * 80) + ko);
                LDSM_X4(al[mt][0], al[mt][1], al[mt][2], al[mt][3],
                        aAl + mt * (16 * 80) + ko);
            }
#pragma unroll
            for (int mt = 0; mt < MT; mt++)
#pragma unroll
                for (int nt = 0; nt < 4; nt++) {
                    MMA_F16(acc[mt][nt], ah[mt], bq[nt]);
                    MMA_F16(acc[mt][nt], al[mt], bq[nt]);
                }
        }
        __syncthreads();
    }

#pragma unroll
    for (int mt = 0; mt < MT; mt++) {
        const int row0 = m0 + wm * (BM / 2) + mt * 16 + g;
#pragma unroll
        for (int nt = 0; nt < 4; nt++) {
            const int col = n0 + wn * 32 + nt * 8 + tig * 2;
            const float b0 = bias[col], b1 = bias[col + 1];
            float2 v0 = make_float2(acc[mt][nt][0] + b0, acc[mt][nt][1] + b1);
            float2 v1 = make_float2(acc[mt][nt][2] + b0, acc[mt][nt][3] + b1);
            *(float2*)&C[(size_t)row0 * N + col]       = v0;
            *(float2*)&C[(size_t)(row0 + 8) * N + col] = v1;
        }
    }
}

// ---------------------------------------------------------------------------
// Persistent-segment HMMA attention with fused rope + fp16 splits.
// grid = (8 segs, 16 heads), 256 threads.  (R8/R9, unchanged)
// ---------------------------------------------------------------------------
#define AQROW   176
#define ASS_LD  268
#define SM_K    0
#define SM_V    45056
#define SM_QH   90112
#define SM_QL   101376
#define SM_SS   112640
#define ATTN_SMEM (112640 + 64 * ASS_LD * 4)

__global__ __launch_bounds__(256, 1)
void attn_mma_kernel(const float* __restrict__ qkv,
                     const float* __restrict__ cosb,
                     const float* __restrict__ sinb,
                     const int* __restrict__ cu,
                     __half* __restrict__ oh,
                     __half* __restrict__ ol) {
    extern __shared__ __align__(16) char sm[];
    const uint32_t sb = smem_to_u32(sm);
    float* sS = (float*)(sm + SM_SS);

    const int tid  = threadIdx.x;
    const int wid  = tid >> 5;
    const int lane = tid & 31;
    const int seg  = blockIdx.x;
    const int head = blockIdx.y;

    const int segStart = cu[seg];
    const int hb = head * HDIM;
    const float scale = rsqrtf((float)HDIM);

    for (int i = tid; i < SEG * 40; i += 256) {
        int r = i / 40, d = i % 40;
        int s = segStart + r;
        float c1 = cosb[s * HDIM + d],      s1 = sinb[s * HDIM + d];
        float c2 = cosb[s * HDIM + d + 40], s2 = sinb[s * HDIM + d + 40];
        size_t gb = (size_t)s * QKV_N + HID + hb + d;
        float k1 = qkv[gb], k2 = qkv[gb + 40];
        __half* kp = (__half*)(sm + SM_K + r * AQROW);
        kp[d]      = __float2half_rn(k1 * c1 - k2 * s1);
        kp[d + 40] = __float2half_rn(k2 * c2 + k1 * s2);
    }
    for (int i = tid; i < SEG * 20; i += 256) {
        int r = i / 20, c = i % 20;
        float4 v = *(const float4*)&qkv[(size_t)(segStart + r) * QKV_N + 2 * HID + hb + c * 4];
        __half2* vp = (__half2*)(sm + SM_V + r * AQROW + c * 8);
        vp[0] = __floats2half2_rn(v.x, v.y);
        vp[1] = __floats2half2_rn(v.z, v.w);
    }

    for (int chunk = 0; chunk < 4; chunk++) {
        const int q0 = segStart + chunk * 64;

        for (int i = tid; i < 64 * 40; i += 256) {
            int r = i / 40, d = i % 40;
            int s = q0 + r;
            float c1 = cosb[s * HDIM + d],      s1 = sinb[s * HDIM + d];
            float c2 = cosb[s * HDIM + d + 40], s2 = sinb[s * HDIM + d + 40];
            size_t gb = (size_t)s * QKV_N + hb + d;
            float q1 = qkv[gb], q2 = qkv[gb + 40];
            float qa = (q1 * c1 - q2 * s1) * scale;
            float qb = (q2 * c2 + q1 * s2) * scale;
            __half* qhp = (__half*)(sm + SM_QH + r * AQROW);
            __half* qlp = (__half*)(sm + SM_QL + r * AQROW);
            __half t;
            t = __float2half_rn(qa); qhp[d]      = t; qlp[d]      = __float2half_rn(qa - __half2float(t));
            t = __float2half_rn(qb); qhp[d + 40] = t; qlp[d + 40] = __float2half_rn(qb - __half2float(t));
        }
        __syncthreads();

        {
            const int wm = wid & 1, wn = wid >> 1;
            float acc[2][8][4];
#pragma unroll
            for (int i = 0; i < 2; i++)
#pragma unroll
                for (int j = 0; j < 8; j++)
#pragma unroll
                    for (int r = 0; r < 4; r++) acc[i][j][r] = 0.f;

            const uint32_t aBase = sb + SM_QH + (uint32_t)(wm * 32 + (lane & 15)) * AQROW
                                   + ((lane >> 4) & 1) * 16;
            const uint32_t bBase = sb + SM_K + (uint32_t)(wn * 64 + (lane & 15)) * AQROW
                                   + ((lane >> 4) & 1) * 16;

#pragma unroll
            for (int ks = 0; ks < 5; ks++) {
                const uint32_t ko = ks * 32;
                uint32_t ah[2][4], al[2][4];
#pragma unroll
                for (int mt = 0; mt < 2; mt++) {
                    LDSM_X4(ah[mt][0], ah[mt][1], ah[mt][2], ah[mt][3],
                            aBase + mt * (16 * AQROW) + ko);
                    LDSM_X4(al[mt][0], al[mt][1], al[mt][2], al[mt][3],
                            aBase + (SM_QL - SM_QH) + mt * (16 * AQROW) + ko);
                }
#pragma unroll
                for (int np = 0; np < 4; np++) {
                    uint32_t bk[2][2];
                    LDSM_X4(bk[0][0], bk[1][0], bk[0][1], bk[1][1],
                            bBase + np * (16 * AQROW) + ko);
#pragma unroll
                    for (int mt = 0; mt < 2; mt++)
#pragma unroll
                        for (int j = 0; j < 2; j++) {
                            MMA_F16(acc[mt][np*2+j], ah[mt], bk[j]);
                            MMA_F16(acc[mt][np*2+j], al[mt], bk[j]);
                        }
                }
            }
#pragma unroll
            for (int mt = 0; mt < 2; mt++) {
                const int r = wm * 32 + mt * 16 + (lane >> 2);
#pragma unroll
                for (int nt = 0; nt < 8; nt++) {
                    const int c = wn * 64 + nt * 8 + 2 * (lane & 3);
                    *(float2*)&sS[r * ASS_LD + c] =
                        make_float2(acc[mt][nt][0], acc[mt][nt][1]);
                    *(float2*)&sS[(r + 8) * ASS_LD + c] =
                        make_float2(acc[mt][nt][2], acc[mt][nt][3]);
                }
            }
        }
        __syncthreads();

        {
            const int r  = tid >> 2;
            const int cl = tid & 3;
            float mx = -1e30f;
#pragma unroll
            for (int j = 0; j < 64; j++)
                mx = fmaxf(mx, sS[r * ASS_LD + cl + 4 * j]);
            mx = fmaxf(mx, __shfl_xor_sync(0xFFFFFFFFu, mx, 1));
            mx = fmaxf(mx, __shfl_xor_sync(0xFFFFFFFFu, mx, 2));
            float sum = 0.f;
#pragma unroll
            for (int j = 0; j < 64; j++) {
                int c = cl + 4 * j;
                float e = __expf(sS[r * ASS_LD + c] - mx);
                sS[r * ASS_LD + c] = e;
                sum += e;
            }
            sum += __shfl_xor_sync(0xFFFFFFFFu, sum, 1);
            sum += __shfl_xor_sync(0xFFFFFFFFu, sum, 2);
            float inv = 1.f / sum;
#pragma unroll
            for (int j = 0; j < 64; j++) sS[r * ASS_LD + cl + 4 * j] *= inv;
        }
        __syncthreads();

        {
            const int wr = wid >> 1, wc = wid & 1;
            float facc[5][4];
#pragma unroll
            for (int i = 0; i < 5; i++)
#pragma unroll
                for (int r = 0; r < 4; r++) facc[i][r] = 0.f;

            const int pr = wr * 16 + (lane >> 2);
            const uint32_t vRowOff = (uint32_t)((lane & 7) + ((lane >> 3) & 1) * 8) * AQROW;
            const uint32_t vColHi  = ((lane >> 4) & 1) * 16;

#pragma unroll
            for (int ks = 0; ks < 16; ks++) {
                const int c = ks * 16 + 2 * (lane & 3);
                float2 p00 = *(float2*)&sS[pr * ASS_LD + c];
                float2 p01 = *(float2*)&sS[pr * ASS_LD + c + 8];
                float2 p10 = *(float2*)&sS[(pr + 8) * ASS_LD + c];
                float2 p11 = *(float2*)&sS[(pr + 8) * ASS_LD + c + 8];
                uint32_t pha[4], pla[4];
                split2h(p00, pha[0], pla[0]);
                split2h(p10, pha[1], pla[1]);
                split2h(p01, pha[2], pla[2]);
                split2h(p11, pha[3], pla[3]);

                const uint32_t vk = sb + SM_V + (uint32_t)(ks * 16) * AQROW + vRowOff;

#pragma unroll
                for (int np = 0; np < 2; np++) {
                    const uint32_t co = (uint32_t)(wc * 40 + np * 16) * 2 + vColHi;
                    uint32_t bv[2][2];
                    LDSM_X4T(bv[0][0], bv[0][1], bv[1][0], bv[1][1], vk + co);
#pragma unroll
                    for (int j = 0; j < 2; j++) {
                        MMA_F16(facc[np*2+j], pha, bv[j]);
                        MMA_F16(facc[np*2+j], pla, bv[j]);
                    }
                }
                {
                    const uint32_t co = (uint32_t)(wc * 40 + 32) * 2;
                    uint32_t b4[2];
                    LDSM_X2T(b4[0], b4[1], vk + co);
                    MMA_F16(facc[4], pha, b4);
                    MMA_F16(facc[4], pla, b4);
                }
            }

            const int row0 = q0 + wr * 16 + (lane >> 2);
#pragma unroll
            for (int nt = 0; nt < 5; nt++) {
                const int col = hb + wc * 40 + nt * 8 + 2 * (lane & 3);
                uint32_t h0, l0, h1, l1;
                split2h(make_float2(facc[nt][0], facc[nt][1]), h0, l0);
                split2h(make_float2(facc[nt][2], facc[nt][3]), h1, l1);
                *(uint32_t*)(oh + (size_t)row0 * HID + col)       = h0;
                *(uint32_t*)(ol + (size_t)row0 * HID + col)       = l0;
                *(uint32_t*)(oh + (size_t)(row0 + 8) * HID + col) = h1;
                *(uint32_t*)(ol + (size_t)(row0 + 8) * HID + col) = l1;
            }
        }
        __syncthreads();
    }
}

// ---------------------------------------------------------------------------
extern "C" void kernel_launch(void* const* d_in, const int* in_sizes, int n_in,
                              void* d_out, int out_size) {
    const float* x      = (const float*)d_in[0];
    const float* cosb   = (const float*)d_in[1];
    const float* sinb   = (const float*)d_in[2];
    const float* W_qkv  = (const float*)d_in[3];
    const float* b_qkv  = (const float*)d_in[4];
    const float* W_out  = (const float*)d_in[5];
    const float* b_out  = (const float*)d_in[6];
    const int*   cu     = (const int*)d_in[7];
    float*       outp   = (float*)d_out;

    float* qkv;
    __half *xh, *xl, *ah, *al, *wq, *wo;
    cudaGetSymbolAddress((void**)&qkv, g_qkv);
    cudaGetSymbolAddress((void**)&xh,  g_xh);
    cudaGetSymbolAddress((void**)&xl,  g_xl);
    cudaGetSymbolAddress((void**)&ah,  g_ah);
    cudaGetSymbolAddress((void**)&al,  g_al);
    cudaGetSymbolAddress((void**)&wq,  g_wq);
    cudaGetSymbolAddress((void**)&wo,  g_wo);

    constexpr int SMEM128 = 2 * (2 * 128 * 80 + 128 * 80);   // 61440
    constexpr int SMEM64  = 2 * (2 * 64 * 80 + 128 * 80);    // 40960

    static bool attr_set = false;
    if (!attr_set) {
        cudaFuncSetAttribute(attn_mma_kernel,
                             cudaFuncAttributeMaxDynamicSharedMemorySize, ATTN_SMEM);
        cudaFuncSetAttribute((const void*)gemm_f16x2_kernel<128, 2>,
                             cudaFuncAttributeMaxDynamicSharedMemorySize, SMEM128);
        cudaFuncSetAttribute((const void*)gemm_f16x2_kernel<64, 3>,
                             cudaFuncAttributeMaxDynamicSharedMemorySize, SMEM64);
        attr_set = true;
    }

    // 0. merged prep
    prep_kernel<<<8960, 256>>>(x, W_qkv, W_out, xh, xl, wq, wo);
    // 1. QKV projection (BM=128, 2 CTA/SM)
    gemm_f16x2_kernel<128, 2><<<dim3(QKV_N / 128, S_LEN / 128), 256, SMEM128>>>(
        S_LEN, QKV_N, HID, xh, xl, wq, b_qkv, qkv);
    // 2. attention (fused rope/splits) -> ah/al
    attn_mma_kernel<<<dim3(NSEG, NHEAD), 256, ATTN_SMEM>>>(
        qkv, cosb, sinb, cu, ah, al);
    // 3. out projection (BM=64, 3 CTA/SM -> all 320 CTAs in one wave)
    gemm_f16x2_kernel<64, 3><<<dim3(HID / 128, S_LEN / 64), 256, SMEM64>>>(
        S_LEN, HID, HID, ah, al, wo, b_out, outp);
}

// round 12
// speedup vs baseline: 1.4870x; 1.4870x over previous
#include <cuda_runtime.h>
#include <cuda_fp16.h>
#include <cstdint>
#include <math.h>

// ===========================================================================
// VisionAttention (sm_103): fp16 2-product HMMA GEMMs (BM templated;
// out-proj BM=64, 2 CTA/SM) + persistent-segment HMMA attention with
// fused rope/splits. 4 launches. (R9 configuration — verified 313.8us.)
// ===========================================================================

#define S_LEN 2048
#define HID   1280
#define NHEAD 16
#define HDIM  80
#define QKV_N (3 * HID)   // 3840
#define SEG   256
#define NSEG  8

// ---------------- device scratch ----------------
__device__ __align__(256) float g_qkv[S_LEN * QKV_N];
__device__ __align__(256) __half g_xh[S_LEN * HID];
__device__ __align__(256) __half g_xl[S_LEN * HID];
__device__ __align__(256) __half g_ah[S_LEN * HID];
__device__ __align__(256) __half g_al[S_LEN * HID];
__device__ __align__(256) __half g_wq[QKV_N * HID];   // [N][K] fp16
__device__ __align__(256) __half g_wo[HID * HID];

__device__ __forceinline__ uint32_t smem_to_u32(const void* p) {
    uint32_t a;
    asm("{ .reg .u64 t; cvta.to.shared.u64 t, %1; cvt.u32.u64 %0, t; }"
        : "=r"(a) : "l"(p));
    return a;
}

#define CP_ASYNC16(sa, gp) \
    asm volatile("cp.async.cg.shared.global [%0], [%1], 16;" \
        :: "r"(sa), "l"(gp) : "memory")
#define CP_COMMIT() asm volatile("cp.async.commit_group;" ::: "memory")

#define MMA_F16(ac, a, b) \
    asm volatile("mma.sync.aligned.m16n8k16.row.col.f32.f16.f16.f32 " \
        "{%0,%1,%2,%3},{%4,%5,%6,%7},{%8,%9},{%0,%1,%2,%3};" \
        : "+f"((ac)[0]), "+f"((ac)[1]), "+f"((ac)[2]), "+f"((ac)[3]) \
        : "r"((a)[0]), "r"((a)[1]), "r"((a)[2]), "r"((a)[3]), \
          "r"((b)[0]), "r"((b)[1]))

#define LDSM_X4(r0, r1, r2, r3, addr) \
    asm volatile("ldmatrix.sync.aligned.m8n8.x4.shared.b16 {%0,%1,%2,%3}, [%4];" \
        : "=r"(r0), "=r"(r1), "=r"(r2), "=r"(r3) : "r"(addr))
#define LDSM_X4T(r0, r1, r2, r3, addr) \
    asm volatile("ldmatrix.sync.aligned.m8n8.x4.trans.shared.b16 {%0,%1,%2,%3}, [%4];" \
        : "=r"(r0), "=r"(r1), "=r"(r2), "=r"(r3) : "r"(addr))
#define LDSM_X2T(r0, r1, addr) \
    asm volatile("ldmatrix.sync.aligned.m8n8.x2.trans.shared.b16 {%0,%1}, [%2];" \
        : "=r"(r0), "=r"(r1) : "r"(addr))

__device__ __forceinline__ void split2h(float2 p, uint32_t& hi, uint32_t& lo) {
    __half hx = __float2half_rn(p.x);
    __half hy = __float2half_rn(p.y);
    __half lx = __float2half_rn(p.x - __half2float(hx));
    __half ly = __float2half_rn(p.y - __half2float(hy));
    hi = (uint32_t)__half_as_ushort(hx) | ((uint32_t)__half_as_ushort(hy) << 16);
    lo = (uint32_t)__half_as_ushort(lx) | ((uint32_t)__half_as_ushort(ly) << 16);
}

// ---------------------------------------------------------------------------
// Merged prep: 1 launch.
//   blocks [0, 2560)   : split x -> xh/xl
//   blocks [2560, 7360): transpose W_qkv -> wq
//   blocks [7360, 8960): transpose W_out -> wo
// ---------------------------------------------------------------------------
__device__ __forceinline__ void transpose_tile(const float* __restrict__ W,
                                               __half* __restrict__ Wt,
                                               int K, int N, int bn, int bk,
                                               int tx, int ty, float* t) {
#pragma unroll
    for (int i = 0; i < 4; i++)
        t[(ty + i * 8) * 33 + tx] = W[(size_t)(bk * 32 + ty + i * 8) * N + bn * 32 + tx];
    __syncthreads();
#pragma unroll
    for (int i = 0; i < 4; i++)
        Wt[(size_t)(bn * 32 + ty + i * 8) * K + bk * 32 + tx] =
            __float2half_rn(t[tx * 33 + ty + i * 8]);
}

__global__ void prep_kernel(const float* __restrict__ x,
                            const float* __restrict__ Wq,
                            const float* __restrict__ Wo,
                            __half* __restrict__ xh, __half* __restrict__ xl,
                            __half* __restrict__ wq, __half* __restrict__ wo) {
    __shared__ float t[32 * 33];
    const int b = blockIdx.x;
    const int tid = threadIdx.x;
    if (b < 2560) {
        int i = (b * 256 + tid) * 4;
        float4 a = *(const float4*)&x[i];
        uint32_t h0, l0, h1, l1;
        split2h(make_float2(a.x, a.y), h0, l0);
        split2h(make_float2(a.z, a.w), h1, l1);
        ((uint32_t*)xh)[i >> 1]       = h0;
        ((uint32_t*)xh)[(i >> 1) + 1] = h1;
        ((uint32_t*)xl)[i >> 1]       = l0;
        ((uint32_t*)xl)[(i >> 1) + 1] = l1;
    } else if (b < 7360) {
        int j = b - 2560;
        transpose_tile(Wq, wq, HID, QKV_N, j % 120, j / 120, tid & 31, tid >> 5, t);
    } else {
        int j = b - 7360;
        transpose_tile(Wo, wo, HID, HID, j % 40, j / 40, tid & 31, tid >> 5, t);
    }
}

// ---------------------------------------------------------------------------
// fp16 2-product GEMM, BM templated. BN=128, BK=32, 2-stage, 2 CTA/SM.
// ---------------------------------------------------------------------------
template <int BM>
__global__ __launch_bounds__(256, 2)
void gemm_f16x2_kernel(int M, int N, int K,
                       const __half* __restrict__ Ah,
                       const __half* __restrict__ Al,
                       const __half* __restrict__ B,
                       const float* __restrict__ bias,
                       float* __restrict__ C) {
    constexpr int MT      = BM / 32;
    constexpr int A_TILE  = BM * 80;
    constexpr int B_TILE  = 128 * 80;
    constexpr int STAGE   = 2 * A_TILE + B_TILE;
    constexpr int A_CHUNK = BM * 8;
    constexpr int CP_IT   = (A_CHUNK + 512) / 256;

    extern __shared__ __align__(16) char smem[];
    const uint32_t sbase = smem_to_u32(smem);

    const int tid  = threadIdx.x;
    const int wid  = tid >> 5;
    const int lane = tid & 31;
    const int g    = lane >> 2;
    const int tig  = lane & 3;
    const int wm   = wid & 1;
    const int wn   = wid >> 1;
    const int n0   = blockIdx.x * 128;
    const int m0   = blockIdx.y * BM;

    const __half* srcs[3] = {
        Ah + (size_t)m0 * K, Al + (size_t)m0 * K, B + (size_t)n0 * K };

    float acc[MT][4][4];
#pragma unroll
    for (int i = 0; i < MT; i++)
#pragma unroll
        for (int j = 0; j < 4; j++)
#pragma unroll
            for (int r = 0; r < 4; r++) acc[i][j][r] = 0.f;

    const int KT = K / 32;

    auto issue_stage = [&](int buf, int kt) {
#pragma unroll
        for (int i = 0; i < CP_IT; i++) {
            int c = tid + i * 256;
            uint32_t sa;
            const __half* gp;
            if (c < A_CHUNK) {
                int tile = c / (BM * 4);
                int rem  = c % (BM * 4);
                int row  = rem >> 2, c16 = rem & 3;
                gp = srcs[tile] + (size_t)row * K + kt * 32 + c16 * 8;
                sa = sbase + buf * STAGE + tile * A_TILE + row * 80 + c16 * 16;
            } else {
                int cc  = c - A_CHUNK;
                int row = cc >> 2, c16 = cc & 3;
                gp = srcs[2] + (size_t)row * K + kt * 32 + c16 * 8;
                sa = sbase + buf * STAGE + 2 * A_TILE + row * 80 + c16 * 16;
            }
            CP_ASYNC16(sa, gp);
        }
        CP_COMMIT();
    };

    const uint32_t aOff = (uint32_t)(wm * (BM / 2) + (lane & 15)) * 80 + ((lane >> 4) & 1) * 16;
    const uint32_t bOff = (uint32_t)(wn * 32 + (lane & 15)) * 80 + ((lane >> 4) & 1) * 16;

    issue_stage(0, 0);

    for (int kt = 0; kt < KT; kt++) {
        const int buf = kt & 1;
        if (kt + 1 < KT) {
            issue_stage(buf ^ 1, kt + 1);
            asm volatile("cp.async.wait_group 1;" ::: "memory");
        } else {
            asm volatile("cp.async.wait_group 0;" ::: "memory");
        }
        __syncthreads();

        const uint32_t stage = sbase + buf * STAGE;
        const uint32_t aAh = stage + aOff;
        const uint32_t aAl = aAh + A_TILE;
        const uint32_t aB  = stage + 2 * A_TILE + bOff;

#pragma unroll
        for (int ks = 0; ks < 2; ks++) {
            const uint32_t ko = ks * 32;
            uint32_t bq[4][2];
#pragma unroll
            for (int np = 0; np < 2; np++)
                LDSM_X4(bq[np*2][0], bq[np*2+1][0], bq[np*2][1], bq[np*2+1][1],
                        aB + np * (16 * 80) + ko);
            uint32_t ah[MT][4], al[MT][4];
#pragma unroll
            for (int mt = 0; mt < MT; mt++) {
                LDSM_X4(ah[mt][0], ah[mt][1], ah[mt][2], ah[mt][3],
                        aAh + mt * (16 * 80) + ko);
                LDSM_X4(al[mt][0], al[mt][1], al[mt][2], al[mt][3],
                        aAl + mt * (16 * 80) + ko);
            }
#pragma unroll
            for (int mt = 0; mt < MT; mt++)
#pragma unroll
                for (int nt = 0; nt < 4; nt++) {
                    MMA_F16(acc[mt][nt], ah[mt], bq[nt]);
                    MMA_F16(acc[mt][nt], al[mt], bq[nt]);
                }
        }
        __syncthreads();
    }

#pragma unroll
    for (int mt = 0; mt < MT; mt++) {
        const int row0 = m0 + wm * (BM / 2) + mt * 16 + g;
#pragma unroll
        for (int nt = 0; nt < 4; nt++) {
            const int col = n0 + wn * 32 + nt * 8 + tig * 2;
            const float b0 = bias[col], b1 = bias[col + 1];
            float2 v0 = make_float2(acc[mt][nt][0] + b0, acc[mt][nt][1] + b1);
            float2 v1 = make_float2(acc[mt][nt][2] + b0, acc[mt][nt][3] + b1);
            *(float2*)&C[(size_t)row0 * N + col]       = v0;
            *(float2*)&C[(size_t)(row0 + 8) * N + col] = v1;
        }
    }
}

// ---------------------------------------------------------------------------
// Persistent-segment HMMA attention with fused rope + fp16 splits.
// grid = (8 segs, 16 heads), 256 threads.
// ---------------------------------------------------------------------------
#define AQROW   176
#define ASS_LD  268
#define SM_K    0
#define SM_V    45056
#define SM_QH   90112
#define SM_QL   101376
#define SM_SS   112640
#define ATTN_SMEM (112640 + 64 * ASS_LD * 4)

__global__ __launch_bounds__(256, 1)
void attn_mma_kernel(const float* __restrict__ qkv,
                     const float* __restrict__ cosb,
                     const float* __restrict__ sinb,
                     const int* __restrict__ cu,
                     __half* __restrict__ oh,
                     __half* __restrict__ ol) {
    extern __shared__ __align__(16) char sm[];
    const uint32_t sb = smem_to_u32(sm);
    float* sS = (float*)(sm + SM_SS);

    const int tid  = threadIdx.x;
    const int wid  = tid >> 5;
    const int lane = tid & 31;
    const int seg  = blockIdx.x;
    const int head = blockIdx.y;

    const int segStart = cu[seg];
    const int hb = head * HDIM;
    const float scale = rsqrtf((float)HDIM);

    for (int i = tid; i < SEG * 40; i += 256) {
        int r = i / 40, d = i % 40;
        int s = segStart + r;
        float c1 = cosb[s * HDIM + d],      s1 = sinb[s * HDIM + d];
        float c2 = cosb[s * HDIM + d + 40], s2 = sinb[s * HDIM + d + 40];
        size_t gb = (size_t)s * QKV_N + HID + hb + d;
        float k1 = qkv[gb], k2 = qkv[gb + 40];
        __half* kp = (__half*)(sm + SM_K + r * AQROW);
        kp[d]      = __float2half_rn(k1 * c1 - k2 * s1);
        kp[d + 40] = __float2half_rn(k2 * c2 + k1 * s2);
    }
    for (int i = tid; i < SEG * 20; i += 256) {
        int r = i / 20, c = i % 20;
        float4 v = *(const float4*)&qkv[(size_t)(segStart + r) * QKV_N + 2 * HID + hb + c * 4];
        __half2* vp = (__half2*)(sm + SM_V + r * AQROW + c * 8);
        vp[0] = __floats2half2_rn(v.x, v.y);
        vp[1] = __floats2half2_rn(v.z, v.w);
    }

    for (int chunk = 0; chunk < 4; chunk++) {
        const int q0 = segStart + chunk * 64;

        for (int i = tid; i < 64 * 40; i += 256) {
            int r = i / 40, d = i % 40;
            int s = q0 + r;
            float c1 = cosb[s * HDIM + d],      s1 = sinb[s * HDIM + d];
            float c2 = cosb[s * HDIM + d + 40], s2 = sinb[s * HDIM + d + 40];
            size_t gb = (size_t)s * QKV_N + hb + d;
            float q1 = qkv[gb], q2 = qkv[gb + 40];
            float qa = (q1 * c1 - q2 * s1) * scale;
            float qb = (q2 * c2 + q1 * s2) * scale;
            __half* qhp = (__half*)(sm + SM_QH + r * AQROW);
            __half* qlp = (__half*)(sm + SM_QL + r * AQROW);
            __half t;
            t = __float2half_rn(qa); qhp[d]      = t; qlp[d]      = __float2half_rn(qa - __half2float(t));
            t = __float2half_rn(qb); qhp[d + 40] = t; qlp[d + 40] = __float2half_rn(qb - __half2float(t));
        }
        __syncthreads();

        {
            const int wm = wid & 1, wn = wid >> 1;
            float acc[2][8][4];
#pragma unroll
            for (int i = 0; i < 2; i++)
#pragma unroll
                for (int j = 0; j < 8; j++)
#pragma unroll
                    for (int r = 0; r < 4; r++) acc[i][j][r] = 0.f;

            const uint32_t aBase = sb + SM_QH + (uint32_t)(wm * 32 + (lane & 15)) * AQROW
                                   + ((lane >> 4) & 1) * 16;
            const uint32_t bBase = sb + SM_K + (uint32_t)(wn * 64 + (lane & 15)) * AQROW
                                   + ((lane >> 4) & 1) * 16;

#pragma unroll
            for (int ks = 0; ks < 5; ks++) {
                const uint32_t ko = ks * 32;
                uint32_t ah[2][4], al[2][4];
#pragma unroll
                for (int mt = 0; mt < 2; mt++) {
                    LDSM_X4(ah[mt][0], ah[mt][1], ah[mt][2], ah[mt][3],
                            aBase + mt * (16 * AQROW) + ko);
                    LDSM_X4(al[mt][0], al[mt][1], al[mt][2], al[mt][3],
                            aBase + (SM_QL - SM_QH) + mt * (16 * AQROW) + ko);
                }
#pragma unroll
                for (int np = 0; np < 4; np++) {
                    uint32_t bk[2][2];
                    LDSM_X4(bk[0][0], bk[1][0], bk[0][1], bk[1][1],
                            bBase + np * (16 * AQROW) + ko);
#pragma unroll
                    for (int mt = 0; mt < 2; mt++)
#pragma unroll
                        for (int j = 0; j < 2; j++) {
                            MMA_F16(acc[mt][np*2+j], ah[mt], bk[j]);
                            MMA_F16(acc[mt][np*2+j], al[mt], bk[j]);
                        }
                }
            }
#pragma unroll
            for (int mt = 0; mt < 2; mt++) {
                const int r = wm * 32 + mt * 16 + (lane >> 2);
#pragma unroll
                for (int nt = 0; nt < 8; nt++) {
                    const int c = wn * 64 + nt * 8 + 2 * (lane & 3);
                    *(float2*)&sS[r * ASS_LD + c] =
                        make_float2(acc[mt][nt][0], acc[mt][nt][1]);
                    *(float2*)&sS[(r + 8) * ASS_LD + c] =
                        make_float2(acc[mt][nt][2], acc[mt][nt][3]);
                }
            }
        }
        __syncthreads();

        {
            const int r  = tid >> 2;
            const int cl = tid & 3;
            float mx = -1e30f;
#pragma unroll
            for (int j = 0; j < 64; j++)
                mx = fmaxf(mx, sS[r * ASS_LD + cl + 4 * j]);
            mx = fmaxf(mx, __shfl_xor_sync(0xFFFFFFFFu, mx, 1));
            mx = fmaxf(mx, __shfl_xor_sync(0xFFFFFFFFu, mx, 2));
            float sum = 0.f;
#pragma unroll
            for (int j = 0; j < 64; j++) {
                int c = cl + 4 * j;
                float e = __expf(sS[r * ASS_LD + c] - mx);
                sS[r * ASS_LD + c] = e;
                sum += e;
            }
            sum += __shfl_xor_sync(0xFFFFFFFFu, sum, 1);
            sum += __shfl_xor_sync(0xFFFFFFFFu, sum, 2);
            float inv = 1.f / sum;
#pragma unroll
            for (int j = 0; j < 64; j++) sS[r * ASS_LD + cl + 4 * j] *= inv;
        }
        __syncthreads();

        {
            const int wr = wid >> 1, wc = wid & 1;
            float facc[5][4];
#pragma unroll
            for (int i = 0; i < 5; i++)
#pragma unroll
                for (int r = 0; r < 4; r++) facc[i][r] = 0.f;

            const int pr = wr * 16 + (lane >> 2);
            const uint32_t vRowOff = (uint32_t)((lane & 7) + ((lane >> 3) & 1) * 8) * AQROW;
            const uint32_t vColHi  = ((lane >> 4) & 1) * 16;

#pragma unroll
            for (int ks = 0; ks < 16; ks++) {
                const int c = ks * 16 + 2 * (lane & 3);
                float2 p00 = *(float2*)&sS[pr * ASS_LD + c];
                float2 p01 = *(float2*)&sS[pr * ASS_LD + c + 8];
                float2 p10 = *(float2*)&sS[(pr + 8) * ASS_LD + c];
                float2 p11 = *(float2*)&sS[(pr + 8) * ASS_LD + c + 8];
                uint32_t pha[4], pla[4];
                split2h(p00, pha[0], pla[0]);
                split2h(p10, pha[1], pla[1]);
                split2h(p01, pha[2], pla[2]);
                split2h(p11, pha[3], pla[3]);

                const uint32_t vk = sb + SM_V + (uint32_t)(ks * 16) * AQROW + vRowOff;

#pragma unroll
                for (int np = 0; np < 2; np++) {
                    const uint32_t co = (uint32_t)(wc * 40 + np * 16) * 2 + vColHi;
                    uint32_t bv[2][2];
                    LDSM_X4T(bv[0][0], bv[0][1], bv[1][0], bv[1][1], vk + co);
#pragma unroll
                    for (int j = 0; j < 2; j++) {
                        MMA_F16(facc[np*2+j], pha, bv[j]);
                        MMA_F16(facc[np*2+j], pla, bv[j]);
                    }
                }
                {
                    const uint32_t co = (uint32_t)(wc * 40 + 32) * 2;
                    uint32_t b4[2];
                    LDSM_X2T(b4[0], b4[1], vk + co);
                    MMA_F16(facc[4], pha, b4);
                    MMA_F16(facc[4], pla, b4);
                }
            }

            const int row0 = q0 + wr * 16 + (lane >> 2);
#pragma unroll
            for (int nt = 0; nt < 5; nt++) {
                const int col = hb + wc * 40 + nt * 8 + 2 * (lane & 3);
                uint32_t h0, l0, h1, l1;
                split2h(make_float2(facc[nt][0], facc[nt][1]), h0, l0);
                split2h(make_float2(facc[nt][2], facc[nt][3]), h1, l1);
                *(uint32_t*)(oh + (size_t)row0 * HID + col)       = h0;
                *(uint32_t*)(ol + (size_t)row0 * HID + col)       = l0;
                *(uint32_t*)(oh + (size_t)(row0 + 8) * HID + col) = h1;
                *(uint32_t*)(ol + (size_t)(row0 + 8) * HID + col) = l1;
            }
        }
        __syncthreads();
    }
}

// ---------------------------------------------------------------------------
extern "C" void kernel_launch(void* const* d_in, const int* in_sizes, int n_in,
                              void* d_out, int out_size) {
    const float* x      = (const float*)d_in[0];
    const float* cosb   = (const float*)d_in[1];
    const float* sinb   = (const float*)d_in[2];
    const float* W_qkv  = (const float*)d_in[3];
    const float* b_qkv  = (const float*)d_in[4];
    const float* W_out  = (const float*)d_in[5];
    const float* b_out  = (const float*)d_in[6];
    const int*   cu     = (const int*)d_in[7];
    float*       outp   = (float*)d_out;

    float* qkv;
    __half *xh, *xl, *ah, *al, *wq, *wo;
    cudaGetSymbolAddress((void**)&qkv, g_qkv);
    cudaGetSymbolAddress((void**)&xh,  g_xh);
    cudaGetSymbolAddress((void**)&xl,  g_xl);
    cudaGetSymbolAddress((void**)&ah,  g_ah);
    cudaGetSymbolAddress((void**)&al,  g_al);
    cudaGetSymbolAddress((void**)&wq,  g_wq);
    cudaGetSymbolAddress((void**)&wo,  g_wo);

    constexpr int SMEM128 = 2 * (2 * 128 * 80 + 128 * 80);   // 61440
    constexpr int SMEM64  = 2 * (2 * 64 * 80 + 128 * 80);    // 40960

    static bool attr_set = false;
    if (!attr_set) {
        cudaFuncSetAttribute(attn_mma_kernel,
                             cudaFuncAttributeMaxDynamicSharedMemorySize, ATTN_SMEM);
        cudaFuncSetAttribute(gemm_f16x2_kernel<128>,
                             cudaFuncAttributeMaxDynamicSharedMemorySize, SMEM128);
        cudaFuncSetAttribute(gemm_f16x2_kernel<64>,
                             cudaFuncAttributeMaxDynamicSharedMemorySize, SMEM64);
        attr_set = true;
    }

    // 0. merged prep (split x, transpose both weights)
    prep_kernel<<<8960, 256>>>(x, W_qkv, W_out, xh, xl, wq, wo);
    // 1. QKV projection (BM=128, grid 480)
    gemm_f16x2_kernel<128><<<dim3(QKV_N / 128, S_LEN / 128), 256, SMEM128>>>(
        S_LEN, QKV_N, HID, xh, xl, wq, b_qkv, qkv);
    // 2. attention (fused rope/splits) -> ah/al
    attn_mma_kernel<<<dim3(NSEG, NHEAD), 256, ATTN_SMEM>>>(
        qkv, cosb, sinb, cu, ah, al);
    // 3. out projection (BM=64, grid 320)
    gemm_f16x2_kernel<64><<<dim3(HID / 128, S_LEN / 64), 256, SMEM64>>>(
        S_LEN, HID, HID, ah, al, wo, b_out, outp);
}

// round 14
// speedup vs baseline: 2.2212x; 1.4938x over previous
#include <cuda_runtime.h>
#include <cuda_fp16.h>
#include <cstdint>
#include <math.h>

// ===========================================================================
// VisionAttention (sm_103): single-product fp16 HMMA GEMMs (A,B fp16-rounded;
// error budget calibrated) + persistent-segment HMMA attention with fused
// rope/splits (internal q/P hi-lo splits retained). 4 launches.
// ===========================================================================

#define S_LEN 2048
#define HID   1280
#define NHEAD 16
#define HDIM  80
#define QKV_N (3 * HID)   // 3840
#define SEG   256
#define NSEG  8

// ---------------- device scratch ----------------
__device__ __align__(256) float g_qkv[S_LEN * QKV_N];
__device__ __align__(256) __half g_xh[S_LEN * HID];
__device__ __align__(256) __half g_ah[S_LEN * HID];
__device__ __align__(256) __half g_wq[QKV_N * HID];   // [N][K] fp16
__device__ __align__(256) __half g_wo[HID * HID];

__device__ __forceinline__ uint32_t smem_to_u32(const void* p) {
    uint32_t a;
    asm("{ .reg .u64 t; cvta.to.shared.u64 t, %1; cvt.u32.u64 %0, t; }"
        : "=r"(a) : "l"(p));
    return a;
}

#define CP_ASYNC16(sa, gp) \
    asm volatile("cp.async.cg.shared.global [%0], [%1], 16;" \
        :: "r"(sa), "l"(gp) : "memory")
#define CP_COMMIT() asm volatile("cp.async.commit_group;" ::: "memory")

#define MMA_F16(ac, a, b) \
    asm volatile("mma.sync.aligned.m16n8k16.row.col.f32.f16.f16.f32 " \
        "{%0,%1,%2,%3},{%4,%5,%6,%7},{%8,%9},{%0,%1,%2,%3};" \
        : "+f"((ac)[0]), "+f"((ac)[1]), "+f"((ac)[2]), "+f"((ac)[3]) \
        : "r"((a)[0]), "r"((a)[1]), "r"((a)[2]), "r"((a)[3]), \
          "r"((b)[0]), "r"((b)[1]))

#define LDSM_X4(r0, r1, r2, r3, addr) \
    asm volatile("ldmatrix.sync.aligned.m8n8.x4.shared.b16 {%0,%1,%2,%3}, [%4];" \
        : "=r"(r0), "=r"(r1), "=r"(r2), "=r"(r3) : "r"(addr))
#define LDSM_X4T(r0, r1, r2, r3, addr) \
    asm volatile("ldmatrix.sync.aligned.m8n8.x4.trans.shared.b16 {%0,%1,%2,%3}, [%4];" \
        : "=r"(r0), "=r"(r1), "=r"(r2), "=r"(r3) : "r"(addr))
#define LDSM_X2T(r0, r1, addr) \
    asm volatile("ldmatrix.sync.aligned.m8n8.x2.trans.shared.b16 {%0,%1}, [%2];" \
        : "=r"(r0), "=r"(r1) : "r"(addr))

__device__ __forceinline__ void split2h(float2 p, uint32_t& hi, uint32_t& lo) {
    __half hx = __float2half_rn(p.x);
    __half hy = __float2half_rn(p.y);
    __half lx = __float2half_rn(p.x - __half2float(hx));
    __half ly = __float2half_rn(p.y - __half2float(hy));
    hi = (uint32_t)__half_as_ushort(hx) | ((uint32_t)__half_as_ushort(hy) << 16);
    lo = (uint32_t)__half_as_ushort(lx) | ((uint32_t)__half_as_ushort(ly) << 16);
}

// ---------------------------------------------------------------------------
// Merged prep: 1 launch.
//   blocks [0, 2560)   : convert x -> xh (fp16)
//   blocks [2560, 7360): transpose W_qkv -> wq
//   blocks [7360, 8960): transpose W_out -> wo
// ---------------------------------------------------------------------------
__device__ __forceinline__ void transpose_tile(const float* __restrict__ W,
                                               __half* __restrict__ Wt,
                                               int K, int N, int bn, int bk,
                                               int tx, int ty, float* t) {
#pragma unroll
    for (int i = 0; i < 4; i++)
        t[(ty + i * 8) * 33 + tx] = W[(size_t)(bk * 32 + ty + i * 8) * N + bn * 32 + tx];
    __syncthreads();
#pragma unroll
    for (int i = 0; i < 4; i++)
        Wt[(size_t)(bn * 32 + ty + i * 8) * K + bk * 32 + tx] =
            __float2half_rn(t[tx * 33 + ty + i * 8]);
}

__global__ void prep_kernel(const float* __restrict__ x,
                            const float* __restrict__ Wq,
                            const float* __restrict__ Wo,
                            __half* __restrict__ xh,
                            __half* __restrict__ wq, __half* __restrict__ wo) {
    __shared__ float t[32 * 33];
    const int b = blockIdx.x;
    const int tid = threadIdx.x;
    if (b < 2560) {
        int i = (b * 256 + tid) * 4;
        float4 a = *(const float4*)&x[i];
        __half2 h0 = __floats2half2_rn(a.x, a.y);
        __half2 h1 = __floats2half2_rn(a.z, a.w);
        ((__half2*)xh)[i >> 1]       = h0;
        ((__half2*)xh)[(i >> 1) + 1] = h1;
    } else if (b < 7360) {
        int j = b - 2560;
        transpose_tile(Wq, wq, HID, QKV_N, j % 120, j / 120, tid & 31, tid >> 5, t);
    } else {
        int j = b - 7360;
        transpose_tile(Wo, wo, HID, HID, j % 40, j / 40, tid & 31, tid >> 5, t);
    }
}

// ---------------------------------------------------------------------------
// fp16 single-product GEMM: C[M,N] = A[M,K] @ B[N,K]^T + bias
// BM templated. BN=128, BK=32, 2-stage cp.async, 2 CTA/SM.
// ---------------------------------------------------------------------------
template <int BM>
__global__ __launch_bounds__(256, 2)
void gemm_f16x1_kernel(int M, int N, int K,
                       const __half* __restrict__ A,
                       const __half* __restrict__ B,
                       const float* __restrict__ bias,
                       float* __restrict__ C) {
    constexpr int MT      = BM / 32;
    constexpr int A_TILE  = BM * 80;
    constexpr int B_TILE  = 128 * 80;
    constexpr int STAGE   = A_TILE + B_TILE;
    constexpr int A_CHUNK = BM * 4;            // 16B chunks in A tile
    constexpr int CP_IT   = (A_CHUNK + 512) / 256;

    extern __shared__ __align__(16) char smem[];
    const uint32_t sbase = smem_to_u32(smem);

    const int tid  = threadIdx.x;
    const int wid  = tid >> 5;
    const int lane = tid & 31;
    const int g    = lane >> 2;
    const int tig  = lane & 3;
    const int wm   = wid & 1;
    const int wn   = wid >> 1;
    const int n0   = blockIdx.x * 128;
    const int m0   = blockIdx.y * BM;

    const __half* srcA = A + (size_t)m0 * K;
    const __half* srcB = B + (size_t)n0 * K;

    float acc[MT][4][4];
#pragma unroll
    for (int i = 0; i < MT; i++)
#pragma unroll
        for (int j = 0; j < 4; j++)
#pragma unroll
            for (int r = 0; r < 4; r++) acc[i][j][r] = 0.f;

    const int KT = K / 32;

    auto issue_stage = [&](int buf, int kt) {
#pragma unroll
        for (int i = 0; i < CP_IT; i++) {
            int c = tid + i * 256;
            uint32_t sa;
            const __half* gp;
            if (c < A_CHUNK) {
                int row = c >> 2, c16 = c & 3;
                gp = srcA + (size_t)row * K + kt * 32 + c16 * 8;
                sa = sbase + buf * STAGE + row * 80 + c16 * 16;
            } else {
                int cc  = c - A_CHUNK;
                int row = cc >> 2, c16 = cc & 3;
                gp = srcB + (size_t)row * K + kt * 32 + c16 * 8;
                sa = sbase + buf * STAGE + A_TILE + row * 80 + c16 * 16;
            }
            CP_ASYNC16(sa, gp);
        }
        CP_COMMIT();
    };

    const uint32_t aOff = (uint32_t)(wm * (BM / 2) + (lane & 15)) * 80 + ((lane >> 4) & 1) * 16;
    const uint32_t bOff = (uint32_t)(wn * 32 + (lane & 15)) * 80 + ((lane >> 4) & 1) * 16;

    issue_stage(0, 0);

    for (int kt = 0; kt < KT; kt++) {
        const int buf = kt & 1;
        if (kt + 1 < KT) {
            issue_stage(buf ^ 1, kt + 1);
            asm volatile("cp.async.wait_group 1;" ::: "memory");
        } else {
            asm volatile("cp.async.wait_group 0;" ::: "memory");
        }
        __syncthreads();

        const uint32_t stage = sbase + buf * STAGE;
        const uint32_t aA = stage + aOff;
        const uint32_t aB = stage + A_TILE + bOff;

#pragma unroll
        for (int ks = 0; ks < 2; ks++) {
            const uint32_t ko = ks * 32;
            uint32_t bq[4][2];
#pragma unroll
            for (int np = 0; np < 2; np++)
                LDSM_X4(bq[np*2][0], bq[np*2+1][0], bq[np*2][1], bq[np*2+1][1],
                        aB + np * (16 * 80) + ko);
            uint32_t aq[MT][4];
#pragma unroll
            for (int mt = 0; mt < MT; mt++)
                LDSM_X4(aq[mt][0], aq[mt][1], aq[mt][2], aq[mt][3],
                        aA + mt * (16 * 80) + ko);
#pragma unroll
            for (int mt = 0; mt < MT; mt++)
#pragma unroll
                for (int nt = 0; nt < 4; nt++)
                    MMA_F16(acc[mt][nt], aq[mt], bq[nt]);
        }
        __syncthreads();
    }

#pragma unroll
    for (int mt = 0; mt < MT; mt++) {
        const int row0 = m0 + wm * (BM / 2) + mt * 16 + g;
#pragma unroll
        for (int nt = 0; nt < 4; nt++) {
            const int col = n0 + wn * 32 + nt * 8 + tig * 2;
            const float b0 = bias[col], b1 = bias[col + 1];
            float2 v0 = make_float2(acc[mt][nt][0] + b0, acc[mt][nt][1] + b1);
            float2 v1 = make_float2(acc[mt][nt][2] + b0, acc[mt][nt][3] + b1);
            *(float2*)&C[(size_t)row0 * N + col]       = v0;
            *(float2*)&C[(size_t)(row0 + 8) * N + col] = v1;
        }
    }
}

// ---------------------------------------------------------------------------
// Persistent-segment HMMA attention with fused rope + fp16 splits.
// grid = (8 segs, 16 heads), 256 threads. Internal q/P hi-lo splits kept;
// output written as single fp16 plane (oh).
// ---------------------------------------------------------------------------
#define AQROW   176
#define ASS_LD  268
#define SM_K    0
#define SM_V    45056
#define SM_QH   90112
#define SM_QL   101376
#define SM_SS   112640
#define ATTN_SMEM (112640 + 64 * ASS_LD * 4)

__global__ __launch_bounds__(256, 1)
void attn_mma_kernel(const float* __restrict__ qkv,
                     const float* __restrict__ cosb,
                     const float* __restrict__ sinb,
                     const int* __restrict__ cu,
                     __half* __restrict__ oh) {
    extern __shared__ __align__(16) char sm[];
    const uint32_t sb = smem_to_u32(sm);
    float* sS = (float*)(sm + SM_SS);

    const int tid  = threadIdx.x;
    const int wid  = tid >> 5;
    const int lane = tid & 31;
    const int seg  = blockIdx.x;
    const int head = blockIdx.y;

    const int segStart = cu[seg];
    const int hb = head * HDIM;
    const float scale = rsqrtf((float)HDIM);

    for (int i = tid; i < SEG * 40; i += 256) {
        int r = i / 40, d = i % 40;
        int s = segStart + r;
        float c1 = cosb[s * HDIM + d],      s1 = sinb[s * HDIM + d];
        float c2 = cosb[s * HDIM + d + 40], s2 = sinb[s * HDIM + d + 40];
        size_t gb = (size_t)s * QKV_N + HID + hb + d;
        float k1 = qkv[gb], k2 = qkv[gb + 40];
        __half* kp = (__half*)(sm + SM_K + r * AQROW);
        kp[d]      = __float2half_rn(k1 * c1 - k2 * s1);
        kp[d + 40] = __float2half_rn(k2 * c2 + k1 * s2);
    }
    for (int i = tid; i < SEG * 20; i += 256) {
        int r = i / 20, c = i % 20;
        float4 v = *(const float4*)&qkv[(size_t)(segStart + r) * QKV_N + 2 * HID + hb + c * 4];
        __half2* vp = (__half2*)(sm + SM_V + r * AQROW + c * 8);
        vp[0] = __floats2half2_rn(v.x, v.y);
        vp[1] = __floats2half2_rn(v.z, v.w);
    }

    for (int chunk = 0; chunk < 4; chunk++) {
        const int q0 = segStart + chunk * 64;

        for (int i = tid; i < 64 * 40; i += 256) {
            int r = i / 40, d = i % 40;
            int s = q0 + r;
            float c1 = cosb[s * HDIM + d],      s1 = sinb[s * HDIM + d];
            float c2 = cosb[s * HDIM + d + 40], s2 = sinb[s * HDIM + d + 40];
            size_t gb = (size_t)s * QKV_N + hb + d;
            float q1 = qkv[gb], q2 = qkv[gb + 40];
            float qa = (q1 * c1 - q2 * s1) * scale;
            float qb = (q2 * c2 + q1 * s2) * scale;
            __half* qhp = (__half*)(sm + SM_QH + r * AQROW);
            __half* qlp = (__half*)(sm + SM_QL + r * AQROW);
            __half t;
            t = __float2half_rn(qa); qhp[d]      = t; qlp[d]      = __float2half_rn(qa - __half2float(t));
            t = __float2half_rn(qb); qhp[d + 40] = t; qlp[d + 40] = __float2half_rn(qb - __half2float(t));
        }
        __syncthreads();

        {
            const int wm = wid & 1, wn = wid >> 1;
            float acc[2][8][4];
#pragma unroll
            for (int i = 0; i < 2; i++)
#pragma unroll
                for (int j = 0; j < 8; j++)
#pragma unroll
                    for (int r = 0; r < 4; r++) acc[i][j][r] = 0.f;

            const uint32_t aBase = sb + SM_QH + (uint32_t)(wm * 32 + (lane & 15)) * AQROW
                                   + ((lane >> 4) & 1) * 16;
            const uint32_t bBase = sb + SM_K + (uint32_t)(wn * 64 + (lane & 15)) * AQROW
                                   + ((lane >> 4) & 1) * 16;

#pragma unroll
            for (int ks = 0; ks < 5; ks++) {
                const uint32_t ko = ks * 32;
                uint32_t ah[2][4], al[2][4];
#pragma unroll
                for (int mt = 0; mt < 2; mt++) {
                    LDSM_X4(ah[mt][0], ah[mt][1], ah[mt][2], ah[mt][3],
                            aBase + mt * (16 * AQROW) + ko);
                    LDSM_X4(al[mt][0], al[mt][1], al[mt][2], al[mt][3],
                            aBase + (SM_QL - SM_QH) + mt * (16 * AQROW) + ko);
                }
#pragma unroll
                for (int np = 0; np < 4; np++) {
                    uint32_t bk[2][2];
                    LDSM_X4(bk[0][0], bk[1][0], bk[0][1], bk[1][1],
                            bBase + np * (16 * AQROW) + ko);
#pragma unroll
                    for (int mt = 0; mt < 2; mt++)
#pragma unroll
                        for (int j = 0; j < 2; j++) {
                            MMA_F16(acc[mt][np*2+j], ah[mt], bk[j]);
                            MMA_F16(acc[mt][np*2+j], al[mt], bk[j]);
                        }
                }
            }
#pragma unroll
            for (int mt = 0; mt < 2; mt++) {
                const int r = wm * 32 + mt * 16 + (lane >> 2);
#pragma unroll
                for (int nt = 0; nt < 8; nt++) {
                    const int c = wn * 64 + nt * 8 + 2 * (lane & 3);
                    *(float2*)&sS[r * ASS_LD + c] =
                        make_float2(acc[mt][nt][0], acc[mt][nt][1]);
                    *(float2*)&sS[(r + 8) * ASS_LD + c] =
                        make_float2(acc[mt][nt][2], acc[mt][nt][3]);
                }
            }
        }
        __syncthreads();

        {
            const int r  = tid >> 2;
            const int cl = tid & 3;
            float mx = -1e30f;
#pragma unroll
            for (int j = 0; j < 64; j++)
                mx = fmaxf(mx, sS[r * ASS_LD + cl + 4 * j]);
            mx = fmaxf(mx, __shfl_xor_sync(0xFFFFFFFFu, mx, 1));
            mx = fmaxf(mx, __shfl_xor_sync(0xFFFFFFFFu, mx, 2));
            float sum = 0.f;
#pragma unroll
            for (int j = 0; j < 64; j++) {
                int c = cl + 4 * j;
                float e = __expf(sS[r * ASS_LD + c] - mx);
                sS[r * ASS_LD + c] = e;
                sum += e;
            }
            sum += __shfl_xor_sync(0xFFFFFFFFu, sum, 1);
            sum += __shfl_xor_sync(0xFFFFFFFFu, sum, 2);
            float inv = 1.f / sum;
#pragma unroll
            for (int j = 0; j < 64; j++) sS[r * ASS_LD + cl + 4 * j] *= inv;
        }
        __syncthreads();

        {
            const int wr = wid >> 1, wc = wid & 1;
            float facc[5][4];
#pragma unroll
            for (int i = 0; i < 5; i++)
#pragma unroll
                for (int r = 0; r < 4; r++) facc[i][r] = 0.f;

            const int pr = wr * 16 + (lane >> 2);
            const uint32_t vRowOff = (uint32_t)((lane & 7) + ((lane >> 3) & 1) * 8) * AQROW;
            const uint32_t vColHi  = ((lane >> 4) & 1) * 16;

#pragma unroll
            for (int ks = 0; ks < 16; ks++) {
                const int c = ks * 16 + 2 * (lane & 3);
                float2 p00 = *(float2*)&sS[pr * ASS_LD + c];
                float2 p01 = *(float2*)&sS[pr * ASS_LD + c + 8];
                float2 p10 = *(float2*)&sS[(pr + 8) * ASS_LD + c];
                float2 p11 = *(float2*)&sS[(pr + 8) * ASS_LD + c + 8];
                uint32_t pha[4], pla[4];
                split2h(p00, pha[0], pla[0]);
                split2h(p10, pha[1], pla[1]);
                split2h(p01, pha[2], pla[2]);
                split2h(p11, pha[3], pla[3]);

                const uint32_t vk = sb + SM_V + (uint32_t)(ks * 16) * AQROW + vRowOff;

#pragma unroll
                for (int np = 0; np < 2; np++) {
                    const uint32_t co = (uint32_t)(wc * 40 + np * 16) * 2 + vColHi;
                    uint32_t bv[2][2];
                    LDSM_X4T(bv[0][0], bv[0][1], bv[1][0], bv[1][1], vk + co);
#pragma unroll
                    for (int j = 0; j < 2; j++) {
                        MMA_F16(facc[np*2+j], pha, bv[j]);
                        MMA_F16(facc[np*2+j], pla, bv[j]);
                    }
                }
                {
                    const uint32_t co = (uint32_t)(wc * 40 + 32) * 2;
                    uint32_t b4[2];
                    LDSM_X2T(b4[0], b4[1], vk + co);
                    MMA_F16(facc[4], pha, b4);
                    MMA_F16(facc[4], pla, b4);
                }
            }

            const int row0 = q0 + wr * 16 + (lane >> 2);
#pragma unroll
            for (int nt = 0; nt < 5; nt++) {
                const int col = hb + wc * 40 + nt * 8 + 2 * (lane & 3);
                __half2 h0 = __floats2half2_rn(facc[nt][0], facc[nt][1]);
                __half2 h1 = __floats2half2_rn(facc[nt][2], facc[nt][3]);
                *(__half2*)(oh + (size_t)row0 * HID + col)       = h0;
                *(__half2*)(oh + (size_t)(row0 + 8) * HID + col) = h1;
            }
        }
        __syncthreads();
    }
}

// ---------------------------------------------------------------------------
extern "C" void kernel_launch(void* const* d_in, const int* in_sizes, int n_in,
                              void* d_out, int out_size) {
    const float* x      = (const float*)d_in[0];
    const float* cosb   = (const float*)d_in[1];
    const float* sinb   = (const float*)d_in[2];
    const float* W_qkv  = (const float*)d_in[3];
    const float* b_qkv  = (const float*)d_in[4];
    const float* W_out  = (const float*)d_in[5];
    const float* b_out  = (const float*)d_in[6];
    const int*   cu     = (const int*)d_in[7];
    float*       outp   = (float*)d_out;

    float* qkv;
    __half *xh, *ah, *wq, *wo;
    cudaGetSymbolAddress((void**)&qkv, g_qkv);
    cudaGetSymbolAddress((void**)&xh,  g_xh);
    cudaGetSymbolAddress((void**)&ah,  g_ah);
    cudaGetSymbolAddress((void**)&wq,  g_wq);
    cudaGetSymbolAddress((void**)&wo,  g_wo);

    constexpr int SMEM128 = 2 * (128 * 80 + 128 * 80);   // 40960
    constexpr int SMEM64  = 2 * (64 * 80 + 128 * 80);    // 30720

    static bool attr_set = false;
    if (!attr_set) {
        cudaFuncSetAttribute(attn_mma_kernel,
                             cudaFuncAttributeMaxDynamicSharedMemorySize, ATTN_SMEM);
        cudaFuncSetAttribute(gemm_f16x1_kernel<128>,
                             cudaFuncAttributeMaxDynamicSharedMemorySize, SMEM128);
        cudaFuncSetAttribute(gemm_f16x1_kernel<64>,
                             cudaFuncAttributeMaxDynamicSharedMemorySize, SMEM64);
        attr_set = true;
    }

    // 0. merged prep (x -> fp16, transpose both weights)
    prep_kernel<<<8960, 256>>>(x, W_qkv, W_out, xh, wq, wo);
    // 1. QKV projection (BM=128, grid 480, single-product)
    gemm_f16x1_kernel<128><<<dim3(QKV_N / 128, S_LEN / 128), 256, SMEM128>>>(
        S_LEN, QKV_N, HID, xh, wq, b_qkv, qkv);
    // 2. attention (fused rope/splits) -> ah (single fp16 plane)
    attn_mma_kernel<<<dim3(NSEG, NHEAD), 256, ATTN_SMEM>>>(
        qkv, cosb, sinb, cu, ah);
    // 3. out projection (BM=64, grid 320, single-product)
    gemm_f16x1_kernel<64><<<dim3(HID / 128, S_LEN / 64), 256, SMEM64>>>(
        S_LEN, HID, HID, ah, wo, b_out, outp);
}

// round 16
// speedup vs baseline: 2.3249x; 1.0467x over previous
#include <cuda_runtime.h>
#include <cuda_fp16.h>
#include <cstdint>
#include <cstring>
#include <math.h>

// ===========================================================================
// VisionAttention (sm_103): single-product fp16 HMMA everywhere (GEMMs and
// attention; error budget calibrated at ~5.8e-4) + persistent-segment
// attention with fused rope. 4 launches.
// ===========================================================================

#define S_LEN 2048
#define HID   1280
#define NHEAD 16
#define HDIM  80
#define QKV_N (3 * HID)   // 3840
#define SEG   256
#define NSEG  8

// ---------------- device scratch ----------------
__device__ __align__(256) float g_qkv[S_LEN * QKV_N];
__device__ __align__(256) __half g_xh[S_LEN * HID];
__device__ __align__(256) __half g_ah[S_LEN * HID];
__device__ __align__(256) __half g_wq[QKV_N * HID];   // [N][K] fp16
__device__ __align__(256) __half g_wo[HID * HID];

__device__ __forceinline__ uint32_t smem_to_u32(const void* p) {
    uint32_t a;
    asm("{ .reg .u64 t; cvta.to.shared.u64 t, %1; cvt.u32.u64 %0, t; }"
        : "=r"(a) : "l"(p));
    return a;
}

__device__ __forceinline__ uint32_t h2_u32(__half2 h) {
    uint32_t u;
    memcpy(&u, &h, 4);
    return u;
}

#define CP_ASYNC16(sa, gp) \
    asm volatile("cp.async.cg.shared.global [%0], [%1], 16;" \
        :: "r"(sa), "l"(gp) : "memory")
#define CP_COMMIT() asm volatile("cp.async.commit_group;" ::: "memory")

#define MMA_F16(ac, a, b) \
    asm volatile("mma.sync.aligned.m16n8k16.row.col.f32.f16.f16.f32 " \
        "{%0,%1,%2,%3},{%4,%5,%6,%7},{%8,%9},{%0,%1,%2,%3};" \
        : "+f"((ac)[0]), "+f"((ac)[1]), "+f"((ac)[2]), "+f"((ac)[3]) \
        : "r"((a)[0]), "r"((a)[1]), "r"((a)[2]), "r"((a)[3]), \
          "r"((b)[0]), "r"((b)[1]))

#define LDSM_X4(r0, r1, r2, r3, addr) \
    asm volatile("ldmatrix.sync.aligned.m8n8.x4.shared.b16 {%0,%1,%2,%3}, [%4];" \
        : "=r"(r0), "=r"(r1), "=r"(r2), "=r"(r3) : "r"(addr))
#define LDSM_X4T(r0, r1, r2, r3, addr) \
    asm volatile("ldmatrix.sync.aligned.m8n8.x4.trans.shared.b16 {%0,%1,%2,%3}, [%4];" \
        : "=r"(r0), "=r"(r1), "=r"(r2), "=r"(r3) : "r"(addr))
#define LDSM_X2T(r0, r1, addr) \
    asm volatile("ldmatrix.sync.aligned.m8n8.x2.trans.shared.b16 {%0,%1}, [%2];" \
        : "=r"(r0), "=r"(r1) : "r"(addr))

// ---------------------------------------------------------------------------
// Merged prep: 1 launch.
// ---------------------------------------------------------------------------
__device__ __forceinline__ void transpose_tile(const float* __restrict__ W,
                                               __half* __restrict__ Wt,
                                               int K, int N, int bn, int bk,
                                               int tx, int ty, float* t) {
#pragma unroll
    for (int i = 0; i < 4; i++)
        t[(ty + i * 8) * 33 + tx] = W[(size_t)(bk * 32 + ty + i * 8) * N + bn * 32 + tx];
    __syncthreads();
#pragma unroll
    for (int i = 0; i < 4; i++)
        Wt[(size_t)(bn * 32 + ty + i * 8) * K + bk * 32 + tx] =
            __float2half_rn(t[tx * 33 + ty + i * 8]);
}

__global__ void prep_kernel(const float* __restrict__ x,
                            const float* __restrict__ Wq,
                            const float* __restrict__ Wo,
                            __half* __restrict__ xh,
                            __half* __restrict__ wq, __half* __restrict__ wo) {
    __shared__ float t[32 * 33];
    const int b = blockIdx.x;
    const int tid = threadIdx.x;
    if (b < 2560) {
        int i = (b * 256 + tid) * 4;
        float4 a = *(const float4*)&x[i];
        __half2 h0 = __floats2half2_rn(a.x, a.y);
        __half2 h1 = __floats2half2_rn(a.z, a.w);
        ((__half2*)xh)[i >> 1]       = h0;
        ((__half2*)xh)[(i >> 1) + 1] = h1;
    } else if (b < 7360) {
        int j = b - 2560;
        transpose_tile(Wq, wq, HID, QKV_N, j % 120, j / 120, tid & 31, tid >> 5, t);
    } else {
        int j = b - 7360;
        transpose_tile(Wo, wo, HID, HID, j % 40, j / 40, tid & 31, tid >> 5, t);
    }
}

// ---------------------------------------------------------------------------
// fp16 single-product GEMM: C[M,N] = A[M,K] @ B[N,K]^T + bias
// BM templated. BN=128, BK=32, 2-stage cp.async, 2 CTA/SM. (R14 config.)
// ---------------------------------------------------------------------------
template <int BM>
__global__ __launch_bounds__(256, 2)
void gemm_f16x1_kernel(int M, int N, int K,
                       const __half* __restrict__ A,
                       const __half* __restrict__ B,
                       const float* __restrict__ bias,
                       float* __restrict__ C) {
    constexpr int MT      = BM / 32;
    constexpr int A_TILE  = BM * 80;
    constexpr int B_TILE  = 128 * 80;
    constexpr int STAGE   = A_TILE + B_TILE;
    constexpr int A_CHUNK = BM * 4;
    constexpr int CP_IT   = (A_CHUNK + 512) / 256;

    extern __shared__ __align__(16) char smem[];
    const uint32_t sbase = smem_to_u32(smem);

    const int tid  = threadIdx.x;
    const int wid  = tid >> 5;
    const int lane = tid & 31;
    const int g    = lane >> 2;
    const int tig  = lane & 3;
    const int wm   = wid & 1;
    const int wn   = wid >> 1;
    const int n0   = blockIdx.x * 128;
    const int m0   = blockIdx.y * BM;

    const __half* srcA = A + (size_t)m0 * K;
    const __half* srcB = B + (size_t)n0 * K;

    float acc[MT][4][4];
#pragma unroll
    for (int i = 0; i < MT; i++)
#pragma unroll
        for (int j = 0; j < 4; j++)
#pragma unroll
            for (int r = 0; r < 4; r++) acc[i][j][r] = 0.f;

    const int KT = K / 32;

    auto issue_stage = [&](int buf, int kt) {
#pragma unroll
        for (int i = 0; i < CP_IT; i++) {
            int c = tid + i * 256;
            uint32_t sa;
            const __half* gp;
            if (c < A_CHUNK) {
                int row = c >> 2, c16 = c & 3;
                gp = srcA + (size_t)row * K + kt * 32 + c16 * 8;
                sa = sbase + buf * STAGE + row * 80 + c16 * 16;
            } else {
                int cc  = c - A_CHUNK;
                int row = cc >> 2, c16 = cc & 3;
                gp = srcB + (size_t)row * K + kt * 32 + c16 * 8;
                sa = sbase + buf * STAGE + A_TILE + row * 80 + c16 * 16;
            }
            CP_ASYNC16(sa, gp);
        }
        CP_COMMIT();
    };

    const uint32_t aOff = (uint32_t)(wm * (BM / 2) + (lane & 15)) * 80 + ((lane >> 4) & 1) * 16;
    const uint32_t bOff = (uint32_t)(wn * 32 + (lane & 15)) * 80 + ((lane >> 4) & 1) * 16;

    issue_stage(0, 0);

    for (int kt = 0; kt < KT; kt++) {
        const int buf = kt & 1;
        if (kt + 1 < KT) {
            issue_stage(buf ^ 1, kt + 1);
            asm volatile("cp.async.wait_group 1;" ::: "memory");
        } else {
            asm volatile("cp.async.wait_group 0;" ::: "memory");
        }
        __syncthreads();

        const uint32_t stage = sbase + buf * STAGE;
        const uint32_t aA = stage + aOff;
        const uint32_t aB = stage + A_TILE + bOff;

#pragma unroll
        for (int ks = 0; ks < 2; ks++) {
            const uint32_t ko = ks * 32;
            uint32_t bq[4][2];
#pragma unroll
            for (int np = 0; np < 2; np++)
                LDSM_X4(bq[np*2][0], bq[np*2+1][0], bq[np*2][1], bq[np*2+1][1],
                        aB + np * (16 * 80) + ko);
            uint32_t aq[MT][4];
#pragma unroll
            for (int mt = 0; mt < MT; mt++)
                LDSM_X4(aq[mt][0], aq[mt][1], aq[mt][2], aq[mt][3],
                        aA + mt * (16 * 80) + ko);
#pragma unroll
            for (int mt = 0; mt < MT; mt++)
#pragma unroll
                for (int nt = 0; nt < 4; nt++)
                    MMA_F16(acc[mt][nt], aq[mt], bq[nt]);
        }
        __syncthreads();
    }

#pragma unroll
    for (int mt = 0; mt < MT; mt++) {
        const int row0 = m0 + wm * (BM / 2) + mt * 16 + g;
#pragma unroll
        for (int nt = 0; nt < 4; nt++) {
            const int col = n0 + wn * 32 + nt * 8 + tig * 2;
            const float b0 = bias[col], b1 = bias[col + 1];
            float2 v0 = make_float2(acc[mt][nt][0] + b0, acc[mt][nt][1] + b1);
            float2 v1 = make_float2(acc[mt][nt][2] + b0, acc[mt][nt][3] + b1);
            *(float2*)&C[(size_t)row0 * N + col]       = v0;
            *(float2*)&C[(size_t)(row0 + 8) * N + col] = v1;
        }
    }
}

// ---------------------------------------------------------------------------
// Persistent-segment HMMA attention, single-product fp16 (no hi/lo splits).
// grid = (8 segs, 16 heads), 256 threads. Fused rope on q/k loads.
// ---------------------------------------------------------------------------
#define AQROW   176
#define ASS_LD  268
#define SM_K    0
#define SM_V    45056
#define SM_QH   90112
#define SM_SS   101376
#define ATTN_SMEM (101376 + 64 * ASS_LD * 4)   // 169984

__global__ __launch_bounds__(256, 1)
void attn_mma_kernel(const float* __restrict__ qkv,
                     const float* __restrict__ cosb,
                     const float* __restrict__ sinb,
                     const int* __restrict__ cu,
                     __half* __restrict__ oh) {
    extern __shared__ __align__(16) char sm[];
    const uint32_t sb = smem_to_u32(sm);
    float* sS = (float*)(sm + SM_SS);

    const int tid  = threadIdx.x;
    const int wid  = tid >> 5;
    const int lane = tid & 31;
    const int seg  = blockIdx.x;
    const int head = blockIdx.y;

    const int segStart = cu[seg];
    const int hb = head * HDIM;
    const float scale = rsqrtf((float)HDIM);

    // K with fused rope
    for (int i = tid; i < SEG * 40; i += 256) {
        int r = i / 40, d = i % 40;
        int s = segStart + r;
        float c1 = cosb[s * HDIM + d],      s1 = sinb[s * HDIM + d];
        float c2 = cosb[s * HDIM + d + 40], s2 = sinb[s * HDIM + d + 40];
        size_t gb = (size_t)s * QKV_N + HID + hb + d;
        float k1 = qkv[gb], k2 = qkv[gb + 40];
        __half* kp = (__half*)(sm + SM_K + r * AQROW);
        kp[d]      = __float2half_rn(k1 * c1 - k2 * s1);
        kp[d + 40] = __float2half_rn(k2 * c2 + k1 * s2);
    }
    // V
    for (int i = tid; i < SEG * 20; i += 256) {
        int r = i / 20, c = i % 20;
        float4 v = *(const float4*)&qkv[(size_t)(segStart + r) * QKV_N + 2 * HID + hb + c * 4];
        __half2* vp = (__half2*)(sm + SM_V + r * AQROW + c * 8);
        vp[0] = __floats2half2_rn(v.x, v.y);
        vp[1] = __floats2half2_rn(v.z, v.w);
    }

    for (int chunk = 0; chunk < 4; chunk++) {
        const int q0 = segStart + chunk * 64;

        // q chunk: rope + scale, single fp16
        for (int i = tid; i < 64 * 40; i += 256) {
            int r = i / 40, d = i % 40;
            int s = q0 + r;
            float c1 = cosb[s * HDIM + d],      s1 = sinb[s * HDIM + d];
            float c2 = cosb[s * HDIM + d + 40], s2 = sinb[s * HDIM + d + 40];
            size_t gb = (size_t)s * QKV_N + hb + d;
            float q1 = qkv[gb], q2 = qkv[gb + 40];
            __half* qhp = (__half*)(sm + SM_QH + r * AQROW);
            qhp[d]      = __float2half_rn((q1 * c1 - q2 * s1) * scale);
            qhp[d + 40] = __float2half_rn((q2 * c2 + q1 * s2) * scale);
        }
        __syncthreads();

        // QK^T: warp grid 2(m) x 4(n); warp tile 32 x 64
        {
            const int wm = wid & 1, wn = wid >> 1;
            float acc[2][8][4];
#pragma unroll
            for (int i = 0; i < 2; i++)
#pragma unroll
                for (int j = 0; j < 8; j++)
#pragma unroll
                    for (int r = 0; r < 4; r++) acc[i][j][r] = 0.f;

            const uint32_t aBase = sb + SM_QH + (uint32_t)(wm * 32 + (lane & 15)) * AQROW
                                   + ((lane >> 4) & 1) * 16;
            const uint32_t bBase = sb + SM_K + (uint32_t)(wn * 64 + (lane & 15)) * AQROW
                                   + ((lane >> 4) & 1) * 16;

#pragma unroll
            for (int ks = 0; ks < 5; ks++) {
                const uint32_t ko = ks * 32;
                uint32_t aq[2][4];
#pragma unroll
                for (int mt = 0; mt < 2; mt++)
                    LDSM_X4(aq[mt][0], aq[mt][1], aq[mt][2], aq[mt][3],
                            aBase + mt * (16 * AQROW) + ko);
#pragma unroll
                for (int np = 0; np < 4; np++) {
                    uint32_t bk[2][2];
                    LDSM_X4(bk[0][0], bk[1][0], bk[0][1], bk[1][1],
                            bBase + np * (16 * AQROW) + ko);
#pragma unroll
                    for (int mt = 0; mt < 2; mt++)
#pragma unroll
                        for (int j = 0; j < 2; j++)
                            MMA_F16(acc[mt][np*2+j], aq[mt], bk[j]);
                }
            }
#pragma unroll
            for (int mt = 0; mt < 2; mt++) {
                const int r = wm * 32 + mt * 16 + (lane >> 2);
#pragma unroll
                for (int nt = 0; nt < 8; nt++) {
                    const int c = wn * 64 + nt * 8 + 2 * (lane & 3);
                    *(float2*)&sS[r * ASS_LD + c] =
                        make_float2(acc[mt][nt][0], acc[mt][nt][1]);
                    *(float2*)&sS[(r + 8) * ASS_LD + c] =
                        make_float2(acc[mt][nt][2], acc[mt][nt][3]);
                }
            }
        }
        __syncthreads();

        // softmax
        {
            const int r  = tid >> 2;
            const int cl = tid & 3;
            float mx = -1e30f;
#pragma unroll
            for (int j = 0; j < 64; j++)
                mx = fmaxf(mx, sS[r * ASS_LD + cl + 4 * j]);
            mx = fmaxf(mx, __shfl_xor_sync(0xFFFFFFFFu, mx, 1));
            mx = fmaxf(mx, __shfl_xor_sync(0xFFFFFFFFu, mx, 2));
            float sum = 0.f;
#pragma unroll
            for (int j = 0; j < 64; j++) {
                int c = cl + 4 * j;
                float e = __expf(sS[r * ASS_LD + c] - mx);
                sS[r * ASS_LD + c] = e;
                sum += e;
            }
            sum += __shfl_xor_sync(0xFFFFFFFFu, sum, 1);
            sum += __shfl_xor_sync(0xFFFFFFFFu, sum, 2);
            float inv = 1.f / sum;
#pragma unroll
            for (int j = 0; j < 64; j++) sS[r * ASS_LD + cl + 4 * j] *= inv;
        }
        __syncthreads();

        // PV: warp grid 4(m) x 2(n); warp tile 16 rows x 40 d-cols
        {
            const int wr = wid >> 1, wc = wid & 1;
            float facc[5][4];
#pragma unroll
            for (int i = 0; i < 5; i++)
#pragma unroll
                for (int r = 0; r < 4; r++) facc[i][r] = 0.f;

            const int pr = wr * 16 + (lane >> 2);
            const uint32_t vRowOff = (uint32_t)((lane & 7) + ((lane >> 3) & 1) * 8) * AQROW;
            const uint32_t vColHi  = ((lane >> 4) & 1) * 16;

#pragma unroll
            for (int ks = 0; ks < 16; ks++) {
                const int c = ks * 16 + 2 * (lane & 3);
                float2 p00 = *(float2*)&sS[pr * ASS_LD + c];
                float2 p01 = *(float2*)&sS[pr * ASS_LD + c + 8];
                float2 p10 = *(float2*)&sS[(pr + 8) * ASS_LD + c];
                float2 p11 = *(float2*)&sS[(pr + 8) * ASS_LD + c + 8];
                uint32_t pha[4];
                pha[0] = h2_u32(__floats2half2_rn(p00.x, p00.y));
                pha[1] = h2_u32(__floats2half2_rn(p10.x, p10.y));
                pha[2] = h2_u32(__floats2half2_rn(p01.x, p01.y));
                pha[3] = h2_u32(__floats2half2_rn(p11.x, p11.y));

                const uint32_t vk = sb + SM_V + (uint32_t)(ks * 16) * AQROW + vRowOff;

#pragma unroll
                for (int np = 0; np < 2; np++) {
                    const uint32_t co = (uint32_t)(wc * 40 + np * 16) * 2 + vColHi;
                    uint32_t bv[2][2];
                    LDSM_X4T(bv[0][0], bv[0][1], bv[1][0], bv[1][1], vk + co);
#pragma unroll
                    for (int j = 0; j < 2; j++)
                        MMA_F16(facc[np*2+j], pha, bv[j]);
                }
                {
                    const uint32_t co = (uint32_t)(wc * 40 + 32) * 2;
                    uint32_t b4[2];
                    LDSM_X2T(b4[0], b4[1], vk + co);
                    MMA_F16(facc[4], pha, b4);
                }
            }

            const int row0 = q0 + wr * 16 + (lane >> 2);
#pragma unroll
            for (int nt = 0; nt < 5; nt++) {
                const int col = hb + wc * 40 + nt * 8 + 2 * (lane & 3);
                __half2 h0 = __floats2half2_rn(facc[nt][0], facc[nt][1]);
                __half2 h1 = __floats2half2_rn(facc[nt][2], facc[nt][3]);
                *(__half2*)(oh + (size_t)row0 * HID + col)       = h0;
                *(__half2*)(oh + (size_t)(row0 + 8) * HID + col) = h1;
            }
        }
        __syncthreads();
    }
}

// ---------------------------------------------------------------------------
extern "C" void kernel_launch(void* const* d_in, const int* in_sizes, int n_in,
                              void* d_out, int out_size) {
    const float* x      = (const float*)d_in[0];
    const float* cosb   = (const float*)d_in[1];
    const float* sinb   = (const float*)d_in[2];
    const float* W_qkv  = (const float*)d_in[3];
    const float* b_qkv  = (const float*)d_in[4];
    const float* W_out  = (const float*)d_in[5];
    const float* b_out  = (const float*)d_in[6];
    const int*   cu     = (const int*)d_in[7];
    float*       outp   = (float*)d_out;

    float* qkv;
    __half *xh, *ah, *wq, *wo;
    cudaGetSymbolAddress((void**)&qkv, g_qkv);
    cudaGetSymbolAddress((void**)&xh,  g_xh);
    cudaGetSymbolAddress((void**)&ah,  g_ah);
    cudaGetSymbolAddress((void**)&wq,  g_wq);
    cudaGetSymbolAddress((void**)&wo,  g_wo);

    constexpr int SMEM128 = 2 * (128 * 80 + 128 * 80);   // 40960
    constexpr int SMEM64  = 2 * (64 * 80 + 128 * 80);    // 30720

    static bool attr_set = false;
    if (!attr_set) {
        cudaFuncSetAttribute(attn_mma_kernel,
                             cudaFuncAttributeMaxDynamicSharedMemorySize, ATTN_SMEM);
        cudaFuncSetAttribute(gemm_f16x1_kernel<128>,
                             cudaFuncAttributeMaxDynamicSharedMemorySize, SMEM128);
        cudaFuncSetAttribute(gemm_f16x1_kernel<64>,
                             cudaFuncAttributeMaxDynamicSharedMemorySize, SMEM64);
        attr_set = true;
    }

    // 0. merged prep
    prep_kernel<<<8960, 256>>>(x, W_qkv, W_out, xh, wq, wo);
    // 1. QKV projection (BM=128, grid 480)
    gemm_f16x1_kernel<128><<<dim3(QKV_N / 128, S_LEN / 128), 256, SMEM128>>>(
        S_LEN, QKV_N, HID, xh, wq, b_qkv, qkv);
    // 2. attention (fused rope) -> ah
    attn_mma_kernel<<<dim3(NSEG, NHEAD), 256, ATTN_SMEM>>>(
        qkv, cosb, sinb, cu, ah);
    // 3. out projection (BM=64, grid 320)
    gemm_f16x1_kernel<64><<<dim3(HID / 128, S_LEN / 64), 256, SMEM64>>>(
        S_LEN, HID, HID, ah, wo, b_out, outp);
}

// round 17
// speedup vs baseline: 2.3578x; 1.0142x over previous
#include <cuda_runtime.h>
#include <cuda_fp16.h>
#include <cstdint>
#include <cstring>
#include <math.h>

// ===========================================================================
// VisionAttention (sm_103): single-product fp16 HMMA everywhere.
// GEMMs: BK=64 per pipeline stage (two 32-wide sub-tiles, proven swizzle),
// halved barrier count. Persistent-segment attention with fused rope.
// 4 launches.
// ===========================================================================

#define S_LEN 2048
#define HID   1280
#define NHEAD 16
#define HDIM  80
#define QKV_N (3 * HID)   // 3840
#define SEG   256
#define NSEG  8

// ---------------- device scratch ----------------
__device__ __align__(256) float g_qkv[S_LEN * QKV_N];
__device__ __align__(256) __half g_xh[S_LEN * HID];
__device__ __align__(256) __half g_ah[S_LEN * HID];
__device__ __align__(256) __half g_wq[QKV_N * HID];   // [N][K] fp16
__device__ __align__(256) __half g_wo[HID * HID];

__device__ __forceinline__ uint32_t smem_to_u32(const void* p) {
    uint32_t a;
    asm("{ .reg .u64 t; cvta.to.shared.u64 t, %1; cvt.u32.u64 %0, t; }"
        : "=r"(a) : "l"(p));
    return a;
}

__device__ __forceinline__ uint32_t h2_u32(__half2 h) {
    uint32_t u;
    memcpy(&u, &h, 4);
    return u;
}

#define CP_ASYNC16(sa, gp) \
    asm volatile("cp.async.cg.shared.global [%0], [%1], 16;" \
        :: "r"(sa), "l"(gp) : "memory")
#define CP_COMMIT() asm volatile("cp.async.commit_group;" ::: "memory")

#define MMA_F16(ac, a, b) \
    asm volatile("mma.sync.aligned.m16n8k16.row.col.f32.f16.f16.f32 " \
        "{%0,%1,%2,%3},{%4,%5,%6,%7},{%8,%9},{%0,%1,%2,%3};" \
        : "+f"((ac)[0]), "+f"((ac)[1]), "+f"((ac)[2]), "+f"((ac)[3]) \
        : "r"((a)[0]), "r"((a)[1]), "r"((a)[2]), "r"((a)[3]), \
          "r"((b)[0]), "r"((b)[1]))

#define LDSM_X4(r0, r1, r2, r3, addr) \
    asm volatile("ldmatrix.sync.aligned.m8n8.x4.shared.b16 {%0,%1,%2,%3}, [%4];" \
        : "=r"(r0), "=r"(r1), "=r"(r2), "=r"(r3) : "r"(addr))
#define LDSM_X4T(r0, r1, r2, r3, addr) \
    asm volatile("ldmatrix.sync.aligned.m8n8.x4.trans.shared.b16 {%0,%1,%2,%3}, [%4];" \
        : "=r"(r0), "=r"(r1), "=r"(r2), "=r"(r3) : "r"(addr))
#define LDSM_X2T(r0, r1, addr) \
    asm volatile("ldmatrix.sync.aligned.m8n8.x2.trans.shared.b16 {%0,%1}, [%2];" \
        : "=r"(r0), "=r"(r1) : "r"(addr))

// ---------------------------------------------------------------------------
// Merged prep: 1 launch.
// ---------------------------------------------------------------------------
__device__ __forceinline__ void transpose_tile(const float* __restrict__ W,
                                               __half* __restrict__ Wt,
                                               int K, int N, int bn, int bk,
                                               int tx, int ty, float* t) {
#pragma unroll
    for (int i = 0; i < 4; i++)
        t[(ty + i * 8) * 33 + tx] = W[(size_t)(bk * 32 + ty + i * 8) * N + bn * 32 + tx];
    __syncthreads();
#pragma unroll
    for (int i = 0; i < 4; i++)
        Wt[(size_t)(bn * 32 + ty + i * 8) * K + bk * 32 + tx] =
            __float2half_rn(t[tx * 33 + ty + i * 8]);
}

__global__ void prep_kernel(const float* __restrict__ x,
                            const float* __restrict__ Wq,
                            const float* __restrict__ Wo,
                            __half* __restrict__ xh,
                            __half* __restrict__ wq, __half* __restrict__ wo) {
    __shared__ float t[32 * 33];
    const int b = blockIdx.x;
    const int tid = threadIdx.x;
    if (b < 2560) {
        int i = (b * 256 + tid) * 4;
        float4 a = *(const float4*)&x[i];
        __half2 h0 = __floats2half2_rn(a.x, a.y);
        __half2 h1 = __floats2half2_rn(a.z, a.w);
        ((__half2*)xh)[i >> 1]       = h0;
        ((__half2*)xh)[(i >> 1) + 1] = h1;
    } else if (b < 7360) {
        int j = b - 2560;
        transpose_tile(Wq, wq, HID, QKV_N, j % 120, j / 120, tid & 31, tid >> 5, t);
    } else {
        int j = b - 7360;
        transpose_tile(Wo, wo, HID, HID, j % 40, j / 40, tid & 31, tid >> 5, t);
    }
}

// ---------------------------------------------------------------------------
// fp16 single-product GEMM: C[M,N] = A[M,K] @ B[N,K]^T + bias
// BM templated. BN=128, BK=64 per stage (2 x 32-wide sub-tiles),
// 2-stage cp.async, 2 CTA/SM.
// ---------------------------------------------------------------------------
template <int BM>
__global__ __launch_bounds__(256, 2)
void gemm_f16x1_kernel(int M, int N, int K,
                       const __half* __restrict__ A,
                       const __half* __restrict__ B,
                       const float* __restrict__ bias,
                       float* __restrict__ C) {
    constexpr int MT       = BM / 32;
    constexpr int A_TILE   = BM * 80;          // one 32-wide sub-tile
    constexpr int B_TILE   = 128 * 80;
    constexpr int STAGE    = 2 * A_TILE + 2 * B_TILE;
    constexpr int A_CHUNK2 = BM * 8;           // 16B chunks across both A subs
    constexpr int TOT_CH   = A_CHUNK2 + 1024;  // + both B subs
    constexpr int CP_IT    = TOT_CH / 256;

    extern __shared__ __align__(16) char smem[];
    const uint32_t sbase = smem_to_u32(smem);

    const int tid  = threadIdx.x;
    const int wid  = tid >> 5;
    const int lane = tid & 31;
    const int g    = lane >> 2;
    const int tig  = lane & 3;
    const int wm   = wid & 1;
    const int wn   = wid >> 1;
    const int n0   = blockIdx.x * 128;
    const int m0   = blockIdx.y * BM;

    const __half* srcA = A + (size_t)m0 * K;
    const __half* srcB = B + (size_t)n0 * K;

    float acc[MT][4][4];
#pragma unroll
    for (int i = 0; i < MT; i++)
#pragma unroll
        for (int j = 0; j < 4; j++)
#pragma unroll
            for (int r = 0; r < 4; r++) acc[i][j][r] = 0.f;

    const int KT2 = K / 64;   // 20

    auto issue_stage = [&](int buf, int kt2) {
#pragma unroll
        for (int i = 0; i < CP_IT; i++) {
            int c = tid + i * 256;
            uint32_t sa;
            const __half* gp;
            if (c < A_CHUNK2) {
                int sub = c / (BM * 4);
                int rem = c % (BM * 4);
                int row = rem >> 2, c16 = rem & 3;
                gp = srcA + (size_t)row * K + kt2 * 64 + sub * 32 + c16 * 8;
                sa = sbase + buf * STAGE + sub * A_TILE + row * 80 + c16 * 16;
            } else {
                int cc  = c - A_CHUNK2;
                int sub = cc >> 9;              // 512 chunks per B sub
                int rem = cc & 511;
                int row = rem >> 2, c16 = rem & 3;
                gp = srcB + (size_t)row * K + kt2 * 64 + sub * 32 + c16 * 8;
                sa = sbase + buf * STAGE + 2 * A_TILE + sub * B_TILE + row * 80 + c16 * 16;
            }
            CP_ASYNC16(sa, gp);
        }
        CP_COMMIT();
    };

    const uint32_t aOff = (uint32_t)(wm * (BM / 2) + (lane & 15)) * 80 + ((lane >> 4) & 1) * 16;
    const uint32_t bOff = (uint32_t)(wn * 32 + (lane & 15)) * 80 + ((lane >> 4) & 1) * 16;

    issue_stage(0, 0);

    for (int kt2 = 0; kt2 < KT2; kt2++) {
        const int buf = kt2 & 1;
        if (kt2 + 1 < KT2) {
            issue_stage(buf ^ 1, kt2 + 1);
            asm volatile("cp.async.wait_group 1;" ::: "memory");
        } else {
            asm volatile("cp.async.wait_group 0;" ::: "memory");
        }
        __syncthreads();

        const uint32_t stage = sbase + buf * STAGE;

#pragma unroll
        for (int ks4 = 0; ks4 < 4; ks4++) {
            const int sub = ks4 >> 1;
            const uint32_t ko = (ks4 & 1) * 32;
            const uint32_t aA = stage + sub * A_TILE + aOff;
            const uint32_t aB = stage + 2 * A_TILE + sub * B_TILE + bOff;

            uint32_t bq[4][2];
#pragma unroll
            for (int np = 0; np < 2; np++)
                LDSM_X4(bq[np*2][0], bq[np*2+1][0], bq[np*2][1], bq[np*2+1][1],
                        aB + np * (16 * 80) + ko);
            uint32_t aq[MT][4];
#pragma unroll
            for (int mt = 0; mt < MT; mt++)
                LDSM_X4(aq[mt][0], aq[mt][1], aq[mt][2], aq[mt][3],
                        aA + mt * (16 * 80) + ko);
#pragma unroll
            for (int mt = 0; mt < MT; mt++)
#pragma unroll
                for (int nt = 0; nt < 4; nt++)
                    MMA_F16(acc[mt][nt], aq[mt], bq[nt]);
        }
        __syncthreads();
    }

#pragma unroll
    for (int mt = 0; mt < MT; mt++) {
        const int row0 = m0 + wm * (BM / 2) + mt * 16 + g;
#pragma unroll
        for (int nt = 0; nt < 4; nt++) {
            const int col = n0 + wn * 32 + nt * 8 + tig * 2;
            const float b0 = bias[col], b1 = bias[col + 1];
            float2 v0 = make_float2(acc[mt][nt][0] + b0, acc[mt][nt][1] + b1);
            float2 v1 = make_float2(acc[mt][nt][2] + b0, acc[mt][nt][3] + b1);
            *(float2*)&C[(size_t)row0 * N + col]       = v0;
            *(float2*)&C[(size_t)(row0 + 8) * N + col] = v1;
        }
    }
}

// ---------------------------------------------------------------------------
// Persistent-segment HMMA attention, single-product fp16 (R16, unchanged).
// grid = (8 segs, 16 heads), 256 threads. Fused rope on q/k loads.
// ---------------------------------------------------------------------------
#define AQROW   176
#define ASS_LD  268
#define SM_K    0
#define SM_V    45056
#define SM_QH   90112
#define SM_SS   101376
#define ATTN_SMEM (101376 + 64 * ASS_LD * 4)   // 169984

__global__ __launch_bounds__(256, 1)
void attn_mma_kernel(const float* __restrict__ qkv,
                     const float* __restrict__ cosb,
                     const float* __restrict__ sinb,
                     const int* __restrict__ cu,
                     __half* __restrict__ oh) {
    extern __shared__ __align__(16) char sm[];
    const uint32_t sb = smem_to_u32(sm);
    float* sS = (float*)(sm + SM_SS);

    const int tid  = threadIdx.x;
    const int wid  = tid >> 5;
    const int lane = tid & 31;
    const int seg  = blockIdx.x;
    const int head = blockIdx.y;

    const int segStart = cu[seg];
    const int hb = head * HDIM;
    const float scale = rsqrtf((float)HDIM);

    // K with fused rope
    for (int i = tid; i < SEG * 40; i += 256) {
        int r = i / 40, d = i % 40;
        int s = segStart + r;
        float c1 = cosb[s * HDIM + d],      s1 = sinb[s * HDIM + d];
        float c2 = cosb[s * HDIM + d + 40], s2 = sinb[s * HDIM + d + 40];
        size_t gb = (size_t)s * QKV_N + HID + hb + d;
        float k1 = qkv[gb], k2 = qkv[gb + 40];
        __half* kp = (__half*)(sm + SM_K + r * AQROW);
        kp[d]      = __float2half_rn(k1 * c1 - k2 * s1);
        kp[d + 40] = __float2half_rn(k2 * c2 + k1 * s2);
    }
    // V
    for (int i = tid; i < SEG * 20; i += 256) {
        int r = i / 20, c = i % 20;
        float4 v = *(const float4*)&qkv[(size_t)(segStart + r) * QKV_N + 2 * HID + hb + c * 4];
        __half2* vp = (__half2*)(sm + SM_V + r * AQROW + c * 8);
        vp[0] = __floats2half2_rn(v.x, v.y);
        vp[1] = __floats2half2_rn(v.z, v.w);
    }

    for (int chunk = 0; chunk < 4; chunk++) {
        const int q0 = segStart + chunk * 64;

        for (int i = tid; i < 64 * 40; i += 256) {
            int r = i / 40, d = i % 40;
            int s = q0 + r;
            float c1 = cosb[s * HDIM + d],      s1 = sinb[s * HDIM + d];
            float c2 = cosb[s * HDIM + d + 40], s2 = sinb[s * HDIM + d + 40];
            size_t gb = (size_t)s * QKV_N + hb + d;
            float q1 = qkv[gb], q2 = qkv[gb + 40];
            __half* qhp = (__half*)(sm + SM_QH + r * AQROW);
            qhp[d]      = __float2half_rn((q1 * c1 - q2 * s1) * scale);
            qhp[d + 40] = __float2half_rn((q2 * c2 + q1 * s2) * scale);
        }
        __syncthreads();

        // QK^T
        {
            const int wm = wid & 1, wn = wid >> 1;
            float acc[2][8][4];
#pragma unroll
            for (int i = 0; i < 2; i++)
#pragma unroll
                for (int j = 0; j < 8; j++)
#pragma unroll
                    for (int r = 0; r < 4; r++) acc[i][j][r] = 0.f;

            const uint32_t aBase = sb + SM_QH + (uint32_t)(wm * 32 + (lane & 15)) * AQROW
                                   + ((lane >> 4) & 1) * 16;
            const uint32_t bBase = sb + SM_K + (uint32_t)(wn * 64 + (lane & 15)) * AQROW
                                   + ((lane >> 4) & 1) * 16;

#pragma unroll
            for (int ks = 0; ks < 5; ks++) {
                const uint32_t ko = ks * 32;
                uint32_t aq[2][4];
#pragma unroll
                for (int mt = 0; mt < 2; mt++)
                    LDSM_X4(aq[mt][0], aq[mt][1], aq[mt][2], aq[mt][3],
                            aBase + mt * (16 * AQROW) + ko);
#pragma unroll
                for (int np = 0; np < 4; np++) {
                    uint32_t bk[2][2];
                    LDSM_X4(bk[0][0], bk[1][0], bk[0][1], bk[1][1],
                            bBase + np * (16 * AQROW) + ko);
#pragma unroll
                    for (int mt = 0; mt < 2; mt++)
#pragma unroll
                        for (int j = 0; j < 2; j++)
                            MMA_F16(acc[mt][np*2+j], aq[mt], bk[j]);
                }
            }
#pragma unroll
            for (int mt = 0; mt < 2; mt++) {
                const int r = wm * 32 + mt * 16 + (lane >> 2);
#pragma unroll
                for (int nt = 0; nt < 8; nt++) {
                    const int c = wn * 64 + nt * 8 + 2 * (lane & 3);
                    *(float2*)&sS[r * ASS_LD + c] =
                        make_float2(acc[mt][nt][0], acc[mt][nt][1]);
                    *(float2*)&sS[(r + 8) * ASS_LD + c] =
                        make_float2(acc[mt][nt][2], acc[mt][nt][3]);
                }
            }
        }
        __syncthreads();

        // softmax
        {
            const int r  = tid >> 2;
            const int cl = tid & 3;
            float mx = -1e30f;
#pragma unroll
            for (int j = 0; j < 64; j++)
                mx = fmaxf(mx, sS[r * ASS_LD + cl + 4 * j]);
            mx = fmaxf(mx, __shfl_xor_sync(0xFFFFFFFFu, mx, 1));
            mx = fmaxf(mx, __shfl_xor_sync(0xFFFFFFFFu, mx, 2));
            float sum = 0.f;
#pragma unroll
            for (int j = 0; j < 64; j++) {
                int c = cl + 4 * j;
                float e = __expf(sS[r * ASS_LD + c] - mx);
                sS[r * ASS_LD + c] = e;
                sum += e;
            }
            sum += __shfl_xor_sync(0xFFFFFFFFu, sum, 1);
            sum += __shfl_xor_sync(0xFFFFFFFFu, sum, 2);
            float inv = 1.f / sum;
#pragma unroll
            for (int j = 0; j < 64; j++) sS[r * ASS_LD + cl + 4 * j] *= inv;
        }
        __syncthreads();

        // PV
        {
            const int wr = wid >> 1, wc = wid & 1;
            float facc[5][4];
#pragma unroll
            for (int i = 0; i < 5; i++)
#pragma unroll
                for (int r = 0; r < 4; r++) facc[i][r] = 0.f;

            const int pr = wr * 16 + (lane >> 2);
            const uint32_t vRowOff = (uint32_t)((lane & 7) + ((lane >> 3) & 1) * 8) * AQROW;
            const uint32_t vColHi  = ((lane >> 4) & 1) * 16;

#pragma unroll
            for (int ks = 0; ks < 16; ks++) {
                const int c = ks * 16 + 2 * (lane & 3);
                float2 p00 = *(float2*)&sS[pr * ASS_LD + c];
                float2 p01 = *(float2*)&sS[pr * ASS_LD + c + 8];
                float2 p10 = *(float2*)&sS[(pr + 8) * ASS_LD + c];
                float2 p11 = *(float2*)&sS[(pr + 8) * ASS_LD + c + 8];
                uint32_t pha[4];
                pha[0] = h2_u32(__floats2half2_rn(p00.x, p00.y));
                pha[1] = h2_u32(__floats2half2_rn(p10.x, p10.y));
                pha[2] = h2_u32(__floats2half2_rn(p01.x, p01.y));
                pha[3] = h2_u32(__floats2half2_rn(p11.x, p11.y));

                const uint32_t vk = sb + SM_V + (uint32_t)(ks * 16) * AQROW + vRowOff;

#pragma unroll
                for (int np = 0; np < 2; np++) {
                    const uint32_t co = (uint32_t)(wc * 40 + np * 16) * 2 + vColHi;
                    uint32_t bv[2][2];
                    LDSM_X4T(bv[0][0], bv[0][1], bv[1][0], bv[1][1], vk + co);
#pragma unroll
                    for (int j = 0; j < 2; j++)
                        MMA_F16(facc[np*2+j], pha, bv[j]);
                }
                {
                    const uint32_t co = (uint32_t)(wc * 40 + 32) * 2;
                    uint32_t b4[2];
                    LDSM_X2T(b4[0], b4[1], vk + co);
                    MMA_F16(facc[4], pha, b4);
                }
            }

            const int row0 = q0 + wr * 16 + (lane >> 2);
#pragma unroll
            for (int nt = 0; nt < 5; nt++) {
                const int col = hb + wc * 40 + nt * 8 + 2 * (lane & 3);
                __half2 h0 = __floats2half2_rn(facc[nt][0], facc[nt][1]);
                __half2 h1 = __floats2half2_rn(facc[nt][2], facc[nt][3]);
                *(__half2*)(oh + (size_t)row0 * HID + col)       = h0;
                *(__half2*)(oh + (size_t)(row0 + 8) * HID + col) = h1;
            }
        }
        __syncthreads();
    }
}

// ---------------------------------------------------------------------------
extern "C" void kernel_launch(void* const* d_in, const int* in_sizes, int n_in,
                              void* d_out, int out_size) {
    const float* x      = (const float*)d_in[0];
    const float* cosb   = (const float*)d_in[1];
    const float* sinb   = (const float*)d_in[2];
    const float* W_qkv  = (const float*)d_in[3];
    const float* b_qkv  = (const float*)d_in[4];
    const float* W_out  = (const float*)d_in[5];
    const float* b_out  = (const float*)d_in[6];
    const int*   cu     = (const int*)d_in[7];
    float*       outp   = (float*)d_out;

    float* qkv;
    __half *xh, *ah, *wq, *wo;
    cudaGetSymbolAddress((void**)&qkv, g_qkv);
    cudaGetSymbolAddress((void**)&xh,  g_xh);
    cudaGetSymbolAddress((void**)&ah,  g_ah);
    cudaGetSymbolAddress((void**)&wq,  g_wq);
    cudaGetSymbolAddress((void**)&wo,  g_wo);

    constexpr int SMEM128 = 2 * (2 * 128 * 80 + 2 * 128 * 80);   // 81920
    constexpr int SMEM64  = 2 * (2 * 64 * 80 + 2 * 128 * 80);    // 61440

    static bool attr_set = false;
    if (!attr_set) {
        cudaFuncSetAttribute(attn_mma_kernel,
                             cudaFuncAttributeMaxDynamicSharedMemorySize, ATTN_SMEM);
        cudaFuncSetAttribute(gemm_f16x1_kernel<128>,
                             cudaFuncAttributeMaxDynamicSharedMemorySize, SMEM128);
        cudaFuncSetAttribute(gemm_f16x1_kernel<64>,
                             cudaFuncAttributeMaxDynamicSharedMemorySize, SMEM64);
        attr_set = true;
    }

    // 0. merged prep
    prep_kernel<<<8960, 256>>>(x, W_qkv, W_out, xh, wq, wo);
    // 1. QKV projection (BM=128, grid 480, BK=64 stages)
    gemm_f16x1_kernel<128><<<dim3(QKV_N / 128, S_LEN / 128), 256, SMEM128>>>(
        S_LEN, QKV_N, HID, xh, wq, b_qkv, qkv);
    // 2. attention (fused rope) -> ah
    attn_mma_kernel<<<dim3(NSEG, NHEAD), 256, ATTN_SMEM>>>(
        qkv, cosb, sinb, cu, ah);
    // 3. out projection (BM=64, grid 320, BK=64 stages)
    gemm_f16x1_kernel<64><<<dim3(HID / 128, S_LEN / 64), 256, SMEM64>>>(
        S_LEN, HID, HID, ah, wo, b_out, outp);
}